// round 5
// baseline (speedup 1.0000x reference)
#include <cuda_runtime.h>
#include <cuda_fp16.h>
#include <cstdint>

#define RES   128
#define FEAT  32
#define NVOX  (RES * RES * RES)           // 2,097,152 voxels
#define NPTS  (2048 * 1024)               // 2,097,152 points
#define NBIN  4096                        // 16x16x16 spatial bins (8^3 cells each)
#define FULLM 0xffffffffu

// fp16 voxel tensor holding layer-1 pre-activations: vox[v*32+j] = (W1 @ g[:,v])[j]
__device__ __half g_vox16[(size_t)NVOX * FEAT];
// Pre-split lane-major tf32 weight B-fragments.
__device__ float g_wfrag[52 * 128];
// Spatial binning scratch.
__device__ int g_binCount[NBIN];
__device__ int g_binCur[NBIN];
__device__ int g_perm[NPTS];

// ---------------------------------------------------------------------------
__device__ __forceinline__ void mma_tf32(float d[4],
                                         uint32_t a0, uint32_t a1, uint32_t a2, uint32_t a3,
                                         uint32_t b0, uint32_t b1) {
    asm volatile("mma.sync.aligned.m16n8k8.row.col.f32.tf32.tf32.f32 "
                 "{%0,%1,%2,%3}, {%4,%5,%6,%7}, {%8,%9}, {%0,%1,%2,%3};"
                 : "+f"(d[0]), "+f"(d[1]), "+f"(d[2]), "+f"(d[3])
                 : "r"(a0), "r"(a1), "r"(a2), "r"(a3), "r"(b0), "r"(b1));
}

__device__ __forceinline__ void split1(float x, uint32_t& h, uint32_t& l) {
    h = __float_as_uint(x) & 0xffffe000u;
    l = __float_as_uint(x - __uint_as_float(h));
}

__device__ __forceinline__ int bin_of(float cx, float cy, float cz) {
    int x0 = __float2int_rd((cx + 1.0f) * 64.0f - 0.5f);
    int y0 = __float2int_rd((cy + 1.0f) * 64.0f - 0.5f);
    int z0 = __float2int_rd((cz + 1.0f) * 64.0f - 0.5f);
    x0 = min(max(x0, 0), RES - 1) >> 3;
    y0 = min(max(y0, 0), RES - 1) >> 3;
    z0 = min(max(z0, 0), RES - 1) >> 3;
    return (z0 * 16 + y0) * 16 + x0;
}

// ---------------------------------------------------------------------------
// Binning kernels
// ---------------------------------------------------------------------------
__global__ void bin_zero_kernel() {
    g_binCount[blockIdx.x * 1024 + threadIdx.x] = 0;
}

__global__ void __launch_bounds__(256) bin_count_kernel(const float* __restrict__ coord) {
    const int p = blockIdx.x * 256 + threadIdx.x;
    const float cx = coord[p * 3 + 0];
    const float cy = coord[p * 3 + 1];
    const float cz = coord[p * 3 + 2];
    atomicAdd(&g_binCount[bin_of(cx, cy, cz)], 1);
}

__global__ void __launch_bounds__(1024) bin_scan_kernel() {
    __shared__ int s[1024];
    const int tid = threadIdx.x;
    const int4 c = *(const int4*)&g_binCount[tid * 4];
    const int sum = c.x + c.y + c.z + c.w;
    s[tid] = sum;
    __syncthreads();
#pragma unroll
    for (int d = 1; d < 1024; d <<= 1) {
        int v = (tid >= d) ? s[tid - d] : 0;
        __syncthreads();
        s[tid] += v;
        __syncthreads();
    }
    const int excl = s[tid] - sum;
    int4 o;
    o.x = excl;
    o.y = o.x + c.x;
    o.z = o.y + c.y;
    o.w = o.z + c.z;
    *(int4*)&g_binCur[tid * 4] = o;
}

__global__ void __launch_bounds__(256) bin_scatter_kernel(const float* __restrict__ coord) {
    const int p = blockIdx.x * 256 + threadIdx.x;
    const float cx = coord[p * 3 + 0];
    const float cy = coord[p * 3 + 1];
    const float cz = coord[p * 3 + 2];
    const int slot = atomicAdd(&g_binCur[bin_of(cx, cy, cz)], 1);
    g_perm[slot] = p;
}

// ---------------------------------------------------------------------------
// Kernel: build split-tf32 weight B-fragments in mma lane order.
// ---------------------------------------------------------------------------
__global__ void prep_wfrag_kernel(const float* __restrict__ w1, const float* __restrict__ w2,
                                  const float* __restrict__ w3, const float* __restrict__ w4) {
    const int f = blockIdx.x;        // 0..51
    const int lane = threadIdx.x;    // 0..31
    const int g = lane >> 2, t = lane & 3;
    float b0, b1;
    if (f < 48) {
        const int l = f >> 4, r = f & 15, kt = r >> 2, nt = r & 3;
        const float* W = (l == 0) ? w1 : (l == 1) ? w2 : w3;
        b0 = W[(8 * nt + g) * 32 + 8 * kt + t];
        b1 = W[(8 * nt + g) * 32 + 8 * kt + t + 4];
    } else {
        const int kt = f - 48;
        b0 = (g < 4) ? w4[g * 32 + 8 * kt + t]     : 0.0f;
        b1 = (g < 4) ? w4[g * 32 + 8 * kt + t + 4] : 0.0f;
    }
    const uint32_t h0 = __float_as_uint(b0) & 0xffffe000u;
    const uint32_t h1 = __float_as_uint(b1) & 0xffffe000u;
    float4 v;
    v.x = __uint_as_float(h0);
    v.y = __uint_as_float(h1);
    v.z = b0 - v.x;
    v.w = b1 - v.y;
    *(float4*)&g_wfrag[f * 128 + lane * 4] = v;
}

// ---------------------------------------------------------------------------
// Kernel: per-voxel transform grid (C,D,H,W) -> fp16 (D*H*W, 32) of W1 @ v.
// ---------------------------------------------------------------------------
#define TC_STRIDE 264   // 264 mod 32 == 8 -> A-frag reads conflict-free
__global__ void __launch_bounds__(256) voxel_w1_kernel(const float* __restrict__ g) {
    __shared__ float tile[32 * TC_STRIDE];
    __shared__ float swf[16 * 128];
    const int tid = threadIdx.x;
    const int v0 = blockIdx.x * 256;

    {
        const float4* src = (const float4*)g_wfrag;
        float4* dst = (float4*)swf;
        for (int i = tid; i < 16 * 32; i += 256) dst[i] = src[i];
    }
#pragma unroll
    for (int c = 0; c < 32; c++)
        tile[c * TC_STRIDE + tid] = g[(size_t)c * NVOX + v0 + tid];
    __syncthreads();

    const int warp = tid >> 5, lane = tid & 31;
    const int gq = lane >> 2, t = lane & 3;
    const int vb = warp * 32;

    float D[2][4][4];
#pragma unroll
    for (int mt = 0; mt < 2; mt++)
#pragma unroll
        for (int nt = 0; nt < 4; nt++)
#pragma unroll
            for (int i = 0; i < 4; i++) D[mt][nt][i] = 0.0f;

#pragma unroll
    for (int kt = 0; kt < 4; kt++) {
        uint32_t ah[2][4], al[2][4];
#pragma unroll
        for (int mt = 0; mt < 2; mt++) {
            const int r = vb + 16 * mt + gq;
            split1(tile[(8 * kt + t) * TC_STRIDE + r],         ah[mt][0], al[mt][0]);
            split1(tile[(8 * kt + t) * TC_STRIDE + r + 8],     ah[mt][1], al[mt][1]);
            split1(tile[(8 * kt + t + 4) * TC_STRIDE + r],     ah[mt][2], al[mt][2]);
            split1(tile[(8 * kt + t + 4) * TC_STRIDE + r + 8], ah[mt][3], al[mt][3]);
        }
#pragma unroll
        for (int nt = 0; nt < 4; nt++) {
            const float4 B = *(const float4*)&swf[(kt * 4 + nt) * 128 + lane * 4];
            const uint32_t bh0 = __float_as_uint(B.x), bh1 = __float_as_uint(B.y);
            const uint32_t bl0 = __float_as_uint(B.z), bl1 = __float_as_uint(B.w);
#pragma unroll
            for (int mt = 0; mt < 2; mt++) {
                mma_tf32(D[mt][nt], ah[mt][0], ah[mt][1], ah[mt][2], ah[mt][3], bh0, bh1);
                mma_tf32(D[mt][nt], al[mt][0], al[mt][1], al[mt][2], al[mt][3], bh0, bh1);
                mma_tf32(D[mt][nt], ah[mt][0], ah[mt][1], ah[mt][2], ah[mt][3], bl0, bl1);
            }
        }
    }
#pragma unroll
    for (int mt = 0; mt < 2; mt++)
#pragma unroll
        for (int nt = 0; nt < 4; nt++) {
            const int v = v0 + vb + 16 * mt + gq;
            const __half2 p0 = __floats2half2_rn(D[mt][nt][0], D[mt][nt][1]);
            const __half2 p1 = __floats2half2_rn(D[mt][nt][2], D[mt][nt][3]);
            *(__half2*)&g_vox16[(size_t)v * 32 + 8 * nt + 2 * t]       = p0;
            *(__half2*)&g_vox16[(size_t)(v + 8) * 32 + 8 * nt + 2 * t] = p1;
        }
}

// ---------------------------------------------------------------------------
// One mma stage, A built from previous D via warp shuffles.
// ---------------------------------------------------------------------------
template <int FOFF, int BOFF, int NT>
__device__ __forceinline__ void mlp_stage_shfl(const float D[2][4][4], float Dn[2][4][4],
                                               const float* __restrict__ swf,
                                               const float* __restrict__ sb, int lane) {
    const int t = lane & 3;
    const int src0 = (lane & ~3) | (t >> 1);
    const int src2 = src0 + 2;
    const bool odd = (t & 1) != 0;

#pragma unroll
    for (int mt = 0; mt < 2; mt++)
#pragma unroll
        for (int nt = 0; nt < NT; nt++) {
            const float2 bb = *(const float2*)&sb[BOFF + 8 * nt + 2 * t];
            Dn[mt][nt][0] = bb.x; Dn[mt][nt][1] = bb.y;
            Dn[mt][nt][2] = bb.x; Dn[mt][nt][3] = bb.y;
        }
#pragma unroll
    for (int kt = 0; kt < 4; kt++) {
        uint32_t ah[2][4], al[2][4];
#pragma unroll
        for (int mt = 0; mt < 2; mt++) {
            const float r0 = D[mt][kt][0], r1 = D[mt][kt][1];
            const float r2 = D[mt][kt][2], r3 = D[mt][kt][3];
            const float e0 = __shfl_sync(FULLM, r0, src0);
            const float o0 = __shfl_sync(FULLM, r1, src0);
            const float e1 = __shfl_sync(FULLM, r2, src0);
            const float o1 = __shfl_sync(FULLM, r3, src0);
            const float e2 = __shfl_sync(FULLM, r0, src2);
            const float o2 = __shfl_sync(FULLM, r1, src2);
            const float e3 = __shfl_sync(FULLM, r2, src2);
            const float o3 = __shfl_sync(FULLM, r3, src2);
            split1(odd ? o0 : e0, ah[mt][0], al[mt][0]);
            split1(odd ? o1 : e1, ah[mt][1], al[mt][1]);
            split1(odd ? o2 : e2, ah[mt][2], al[mt][2]);
            split1(odd ? o3 : e3, ah[mt][3], al[mt][3]);
        }
#pragma unroll
        for (int nt = 0; nt < NT; nt++) {
            const int fidx = (NT == 4) ? (FOFF + kt * 4 + nt) : (FOFF + kt);
            const float4 B = *(const float4*)&swf[fidx * 128 + lane * 4];
            const uint32_t bh0 = __float_as_uint(B.x), bh1 = __float_as_uint(B.y);
            const uint32_t bl0 = __float_as_uint(B.z), bl1 = __float_as_uint(B.w);
#pragma unroll
            for (int mt = 0; mt < 2; mt++) {
                mma_tf32(Dn[mt][nt], ah[mt][0], ah[mt][1], ah[mt][2], ah[mt][3], bh0, bh1);
                mma_tf32(Dn[mt][nt], al[mt][0], al[mt][1], al[mt][2], al[mt][3], bh0, bh1);
                mma_tf32(Dn[mt][nt], ah[mt][0], ah[mt][1], ah[mt][2], ah[mt][3], bl0, bl1);
            }
        }
    }
}

// ---------------------------------------------------------------------------
// Fused gather (spatially-binned points, fp16 voxels) + layers 2..4 on mma.
// smem: [ wfrag 36*128 | bias 128 | svf 256*36 ] = 55,808 B
// ---------------------------------------------------------------------------
#define SMEM_FLOATS (36 * 128 + 128 + 256 * 36)
#define SMEM_BYTES  (SMEM_FLOATS * 4)

__global__ void __launch_bounds__(256, 2) fused_field_kernel(
    const float* __restrict__ coord,
    const float* __restrict__ b1g, const float* __restrict__ b2g,
    const float* __restrict__ b3g, const float* __restrict__ b4g,
    float* __restrict__ out)
{
    extern __shared__ float sm[];
    float* swf = sm;                      // 36*128
    float* sb  = sm + 36 * 128;           // 128
    float* svf = sm + 36 * 128 + 128;     // 256 * 36

    const int tid = threadIdx.x;
    {
        const float4* src = (const float4*)(g_wfrag + 16 * 128);
        float4* dst = (float4*)swf;
        for (int i = tid; i < 36 * 32; i += 256) dst[i] = src[i];
        if (tid < 32) {
            sb[tid]      = b1g[tid];
            sb[32 + tid] = b2g[tid];
            sb[64 + tid] = b3g[tid];
            sb[96 + tid] = (tid < 4) ? b4g[tid] : 0.0f;
        }
    }
    __syncthreads();

    const int warp  = tid >> 5;
    const int lane  = tid & 31;
    const int chunk = lane & 3;        // 16B slice of the 32 fp16 channels
    const int psub  = lane >> 2;       // point-of-8 in round

    // --- Phase 1: gather h1-pre for binned points -> svf ---
#pragma unroll 1
    for (int s = 0; s < 4; s++) {
        const int q   = (warp << 5) + (s << 3) + psub;
        const int pid = __ldg(&g_perm[blockIdx.x * 256 + q]);

        const float cx = __ldg(&coord[pid * 3 + 0]);
        const float cy = __ldg(&coord[pid * 3 + 1]);
        const float cz = __ldg(&coord[pid * 3 + 2]);

        const float fx = (cx + 1.0f) * 64.0f - 0.5f;
        const float fy = (cy + 1.0f) * 64.0f - 0.5f;
        const float fz = (cz + 1.0f) * 64.0f - 0.5f;

        const float x0f = floorf(fx), y0f = floorf(fy), z0f = floorf(fz);
        const float tx = fx - x0f, ty = fy - y0f, tz = fz - z0f;
        const int x0 = (int)x0f, y0 = (int)y0f, z0 = (int)z0f;

        int   xs[2], ys[2], zs[2];
        float wx[2], wy[2], wz[2];
        xs[0] = max(x0, 0);        xs[1] = min(x0 + 1, RES - 1);
        ys[0] = max(y0, 0);        ys[1] = min(y0 + 1, RES - 1);
        zs[0] = max(z0, 0);        zs[1] = min(z0 + 1, RES - 1);
        wx[0] = (x0 >= 0)          ? (1.0f - tx) : 0.0f;
        wx[1] = (x0 + 1 <= RES - 1)? tx          : 0.0f;
        wy[0] = (y0 >= 0)          ? (1.0f - ty) : 0.0f;
        wy[1] = (y0 + 1 <= RES - 1)? ty          : 0.0f;
        wz[0] = (z0 >= 0)          ? (1.0f - tz) : 0.0f;
        wz[1] = (z0 + 1 <= RES - 1)? tz          : 0.0f;

        float acc[8];
#pragma unroll
        for (int i = 0; i < 8; i++) acc[i] = 0.0f;

#pragma unroll
        for (int kz = 0; kz < 2; kz++)
#pragma unroll
            for (int ky = 0; ky < 2; ky++)
#pragma unroll
                for (int kx = 0; kx < 2; kx++) {
                    const float w = wz[kz] * wy[ky] * wx[kx];
                    const int   vox = ((zs[kz] * RES + ys[ky]) * RES + xs[kx]);
                    const uint4 raw = __ldg(((const uint4*)(g_vox16 + ((size_t)vox << 5))) + chunk);
                    const __half2* h2 = (const __half2*)&raw;
                    const float2 f0 = __half22float2(h2[0]);
                    const float2 f1 = __half22float2(h2[1]);
                    const float2 f2 = __half22float2(h2[2]);
                    const float2 f3 = __half22float2(h2[3]);
                    acc[0] = fmaf(w, f0.x, acc[0]);  acc[1] = fmaf(w, f0.y, acc[1]);
                    acc[2] = fmaf(w, f1.x, acc[2]);  acc[3] = fmaf(w, f1.y, acc[3]);
                    acc[4] = fmaf(w, f2.x, acc[4]);  acc[5] = fmaf(w, f2.y, acc[5]);
                    acc[6] = fmaf(w, f3.x, acc[6]);  acc[7] = fmaf(w, f3.y, acc[7]);
                }
        *(float4*)&svf[q * 36 + chunk * 8]     = make_float4(acc[0], acc[1], acc[2], acc[3]);
        *(float4*)&svf[q * 36 + chunk * 8 + 4] = make_float4(acc[4], acc[5], acc[6], acc[7]);
    }
    __syncwarp();

    // --- Phase 2: layers 2..4 on tensor cores (3xTF32) ---
    const int gq = lane >> 2, t = lane & 3;

    float bA[8];
#pragma unroll
    for (int kt = 0; kt < 4; kt++) {
        bA[2 * kt]     = sb[8 * kt + t];
        bA[2 * kt + 1] = sb[8 * kt + t + 4];
    }

    float D[2][4][4], Dn[2][4][4];

    // stage 1 (= layer 2)
#pragma unroll
    for (int mt = 0; mt < 2; mt++)
#pragma unroll
        for (int nt = 0; nt < 4; nt++) {
            const float2 bb = *(const float2*)&sb[32 + 8 * nt + 2 * t];
            D[mt][nt][0] = bb.x; D[mt][nt][1] = bb.y;
            D[mt][nt][2] = bb.x; D[mt][nt][3] = bb.y;
        }
#pragma unroll
    for (int kt = 0; kt < 4; kt++) {
        uint32_t ah[2][4], al[2][4];
#pragma unroll
        for (int mt = 0; mt < 2; mt++) {
            const int q0 = warp * 32 + 16 * mt + gq;
            const float x0 = fmaxf(svf[q0 * 36 + 8 * kt + t]           + bA[2 * kt],     0.0f);
            const float x1 = fmaxf(svf[(q0 + 8) * 36 + 8 * kt + t]     + bA[2 * kt],     0.0f);
            const float x2 = fmaxf(svf[q0 * 36 + 8 * kt + t + 4]       + bA[2 * kt + 1], 0.0f);
            const float x3 = fmaxf(svf[(q0 + 8) * 36 + 8 * kt + t + 4] + bA[2 * kt + 1], 0.0f);
            split1(x0, ah[mt][0], al[mt][0]);
            split1(x1, ah[mt][1], al[mt][1]);
            split1(x2, ah[mt][2], al[mt][2]);
            split1(x3, ah[mt][3], al[mt][3]);
        }
#pragma unroll
        for (int nt = 0; nt < 4; nt++) {
            const float4 B = *(const float4*)&swf[(kt * 4 + nt) * 128 + lane * 4];
            const uint32_t bh0 = __float_as_uint(B.x), bh1 = __float_as_uint(B.y);
            const uint32_t bl0 = __float_as_uint(B.z), bl1 = __float_as_uint(B.w);
#pragma unroll
            for (int mt = 0; mt < 2; mt++) {
                mma_tf32(D[mt][nt], ah[mt][0], ah[mt][1], ah[mt][2], ah[mt][3], bh0, bh1);
                mma_tf32(D[mt][nt], al[mt][0], al[mt][1], al[mt][2], al[mt][3], bh0, bh1);
                mma_tf32(D[mt][nt], ah[mt][0], ah[mt][1], ah[mt][2], ah[mt][3], bl0, bl1);
            }
        }
    }
#pragma unroll
    for (int mt = 0; mt < 2; mt++)
#pragma unroll
        for (int nt = 0; nt < 4; nt++)
#pragma unroll
            for (int i = 0; i < 4; i++) D[mt][nt][i] = fmaxf(D[mt][nt][i], 0.0f);

    // stage 2 (= layer 3)
    mlp_stage_shfl<16, 64, 4>(D, Dn, swf, sb, lane);
#pragma unroll
    for (int mt = 0; mt < 2; mt++)
#pragma unroll
        for (int nt = 0; nt < 4; nt++)
#pragma unroll
            for (int i = 0; i < 4; i++) Dn[mt][nt][i] = fmaxf(Dn[mt][nt][i], 0.0f);

    // stage 3 (= layer 4), no relu
    mlp_stage_shfl<32, 96, 1>(Dn, D, swf, sb, lane);

    // store through the permutation: rows g, g+8 of each m-tile
    if (t < 2) {
        const int base = blockIdx.x * 256 + warp * 32;
#pragma unroll
        for (int mt = 0; mt < 2; mt++) {
            const int q0 = base + 16 * mt + gq;
            const int p0 = __ldg(&g_perm[q0]);
            const int p1 = __ldg(&g_perm[q0 + 8]);
            *(float2*)&out[p0 * 4 + 2 * t] = make_float2(D[mt][0][0], D[mt][0][1]);
            *(float2*)&out[p1 * 4 + 2 * t] = make_float2(D[mt][0][2], D[mt][0][3]);
        }
    }
}

// ---------------------------------------------------------------------------
extern "C" void kernel_launch(void* const* d_in, const int* in_sizes, int n_in,
                              void* d_out, int out_size)
{
    const float* coord = (const float*)d_in[0];
    const float* grid  = (const float*)d_in[1];
    const float* w1 = (const float*)d_in[2];
    const float* b1 = (const float*)d_in[3];
    const float* w2 = (const float*)d_in[4];
    const float* b2 = (const float*)d_in[5];
    const float* w3 = (const float*)d_in[6];
    const float* b3 = (const float*)d_in[7];
    const float* w4 = (const float*)d_in[8];
    const float* b4 = (const float*)d_in[9];
    float* out = (float*)d_out;

    cudaFuncSetAttribute(fused_field_kernel,
                         cudaFuncAttributeMaxDynamicSharedMemorySize, SMEM_BYTES);

    // binning pipeline (runs concurrently-ish with prep/voxel transform work)
    bin_zero_kernel<<<NBIN / 1024, 1024>>>();
    bin_count_kernel<<<NPTS / 256, 256>>>(coord);
    bin_scan_kernel<<<1, 1024>>>();
    bin_scatter_kernel<<<NPTS / 256, 256>>>(coord);

    prep_wfrag_kernel<<<52, 32>>>(w1, w2, w3, w4);
    voxel_w1_kernel<<<NVOX / 256, 256>>>(grid);

    fused_field_kernel<<<NPTS / 256, 256, SMEM_BYTES>>>(coord, b1, b2, b3, b4, out);
}

// round 6
// speedup vs baseline: 1.4749x; 1.4749x over previous
#include <cuda_runtime.h>
#include <cuda_fp16.h>
#include <cstdint>

#define RES   128
#define FEAT  32
#define NVOX  (RES * RES * RES)           // 2,097,152 voxels
#define NPTS  (2048 * 1024)               // 2,097,152 points
#define FULLM 0xffffffffu

// fp16 voxel tensor holding layer-1 pre-activations: vox[v*32+j] = (W1 @ g[:,v])[j]
__device__ __half g_vox16[(size_t)NVOX * FEAT];
// Pre-split lane-major tf32 weight B-fragments.
__device__ float g_wfrag[52 * 128];

// ---------------------------------------------------------------------------
__device__ __forceinline__ void mma_tf32(float d[4],
                                         uint32_t a0, uint32_t a1, uint32_t a2, uint32_t a3,
                                         uint32_t b0, uint32_t b1) {
    asm volatile("mma.sync.aligned.m16n8k8.row.col.f32.tf32.tf32.f32 "
                 "{%0,%1,%2,%3}, {%4,%5,%6,%7}, {%8,%9}, {%0,%1,%2,%3};"
                 : "+f"(d[0]), "+f"(d[1]), "+f"(d[2]), "+f"(d[3])
                 : "r"(a0), "r"(a1), "r"(a2), "r"(a3), "r"(b0), "r"(b1));
}

__device__ __forceinline__ void split1(float x, uint32_t& h, uint32_t& l) {
    h = __float_as_uint(x) & 0xffffe000u;
    l = __float_as_uint(x - __uint_as_float(h));
}

// ---------------------------------------------------------------------------
// Kernel: build split-tf32 weight B-fragments in mma lane order.
// ---------------------------------------------------------------------------
__global__ void prep_wfrag_kernel(const float* __restrict__ w1, const float* __restrict__ w2,
                                  const float* __restrict__ w3, const float* __restrict__ w4) {
    const int f = blockIdx.x;        // 0..51
    const int lane = threadIdx.x;    // 0..31
    const int g = lane >> 2, t = lane & 3;
    float b0, b1;
    if (f < 48) {
        const int l = f >> 4, r = f & 15, kt = r >> 2, nt = r & 3;
        const float* W = (l == 0) ? w1 : (l == 1) ? w2 : w3;
        b0 = W[(8 * nt + g) * 32 + 8 * kt + t];
        b1 = W[(8 * nt + g) * 32 + 8 * kt + t + 4];
    } else {
        const int kt = f - 48;
        b0 = (g < 4) ? w4[g * 32 + 8 * kt + t]     : 0.0f;
        b1 = (g < 4) ? w4[g * 32 + 8 * kt + t + 4] : 0.0f;
    }
    const uint32_t h0 = __float_as_uint(b0) & 0xffffe000u;
    const uint32_t h1 = __float_as_uint(b1) & 0xffffe000u;
    float4 v;
    v.x = __uint_as_float(h0);
    v.y = __uint_as_float(h1);
    v.z = b0 - v.x;
    v.w = b1 - v.y;
    *(float4*)&g_wfrag[f * 128 + lane * 4] = v;
}

// ---------------------------------------------------------------------------
// Kernel: per-voxel transform grid (C,D,H,W) -> fp16 (D*H*W, 32) of W1 @ v.
// ---------------------------------------------------------------------------
#define TC_STRIDE 264   // 264 mod 32 == 8 -> A-frag reads conflict-free
__global__ void __launch_bounds__(256) voxel_w1_kernel(const float* __restrict__ g) {
    __shared__ float tile[32 * TC_STRIDE];
    __shared__ float swf[16 * 128];
    const int tid = threadIdx.x;
    const int v0 = blockIdx.x * 256;

    {
        const float4* src = (const float4*)g_wfrag;
        float4* dst = (float4*)swf;
        for (int i = tid; i < 16 * 32; i += 256) dst[i] = src[i];
    }
#pragma unroll
    for (int c = 0; c < 32; c++)
        tile[c * TC_STRIDE + tid] = g[(size_t)c * NVOX + v0 + tid];
    __syncthreads();

    const int warp = tid >> 5, lane = tid & 31;
    const int gq = lane >> 2, t = lane & 3;
    const int vb = warp * 32;

    float D[2][4][4];
#pragma unroll
    for (int mt = 0; mt < 2; mt++)
#pragma unroll
        for (int nt = 0; nt < 4; nt++)
#pragma unroll
            for (int i = 0; i < 4; i++) D[mt][nt][i] = 0.0f;

#pragma unroll
    for (int kt = 0; kt < 4; kt++) {
        uint32_t ah[2][4], al[2][4];
#pragma unroll
        for (int mt = 0; mt < 2; mt++) {
            const int r = vb + 16 * mt + gq;
            split1(tile[(8 * kt + t) * TC_STRIDE + r],         ah[mt][0], al[mt][0]);
            split1(tile[(8 * kt + t) * TC_STRIDE + r + 8],     ah[mt][1], al[mt][1]);
            split1(tile[(8 * kt + t + 4) * TC_STRIDE + r],     ah[mt][2], al[mt][2]);
            split1(tile[(8 * kt + t + 4) * TC_STRIDE + r + 8], ah[mt][3], al[mt][3]);
        }
#pragma unroll
        for (int nt = 0; nt < 4; nt++) {
            const float4 B = *(const float4*)&swf[(kt * 4 + nt) * 128 + lane * 4];
            const uint32_t bh0 = __float_as_uint(B.x), bh1 = __float_as_uint(B.y);
            const uint32_t bl0 = __float_as_uint(B.z), bl1 = __float_as_uint(B.w);
#pragma unroll
            for (int mt = 0; mt < 2; mt++) {
                mma_tf32(D[mt][nt], ah[mt][0], ah[mt][1], ah[mt][2], ah[mt][3], bh0, bh1);
                mma_tf32(D[mt][nt], al[mt][0], al[mt][1], al[mt][2], al[mt][3], bh0, bh1);
                mma_tf32(D[mt][nt], ah[mt][0], ah[mt][1], ah[mt][2], ah[mt][3], bl0, bl1);
            }
        }
    }
#pragma unroll
    for (int mt = 0; mt < 2; mt++)
#pragma unroll
        for (int nt = 0; nt < 4; nt++) {
            const int v = v0 + vb + 16 * mt + gq;
            const __half2 p0 = __floats2half2_rn(D[mt][nt][0], D[mt][nt][1]);
            const __half2 p1 = __floats2half2_rn(D[mt][nt][2], D[mt][nt][3]);
            *(__half2*)&g_vox16[(size_t)v * 32 + 8 * nt + 2 * t]       = p0;
            *(__half2*)&g_vox16[(size_t)(v + 8) * 32 + 8 * nt + 2 * t] = p1;
        }
}

// ---------------------------------------------------------------------------
// One mma stage, A built from previous D via warp shuffles.
// ---------------------------------------------------------------------------
template <int FOFF, int BOFF, int NT>
__device__ __forceinline__ void mlp_stage_shfl(const float D[2][4][4], float Dn[2][4][4],
                                               const float* __restrict__ swf,
                                               const float* __restrict__ sb, int lane) {
    const int t = lane & 3;
    const int src0 = (lane & ~3) | (t >> 1);
    const int src2 = src0 + 2;
    const bool odd = (t & 1) != 0;

#pragma unroll
    for (int mt = 0; mt < 2; mt++)
#pragma unroll
        for (int nt = 0; nt < NT; nt++) {
            const float2 bb = *(const float2*)&sb[BOFF + 8 * nt + 2 * t];
            Dn[mt][nt][0] = bb.x; Dn[mt][nt][1] = bb.y;
            Dn[mt][nt][2] = bb.x; Dn[mt][nt][3] = bb.y;
        }
#pragma unroll
    for (int kt = 0; kt < 4; kt++) {
        uint32_t ah[2][4], al[2][4];
#pragma unroll
        for (int mt = 0; mt < 2; mt++) {
            const float r0 = D[mt][kt][0], r1 = D[mt][kt][1];
            const float r2 = D[mt][kt][2], r3 = D[mt][kt][3];
            const float e0 = __shfl_sync(FULLM, r0, src0);
            const float o0 = __shfl_sync(FULLM, r1, src0);
            const float e1 = __shfl_sync(FULLM, r2, src0);
            const float o1 = __shfl_sync(FULLM, r3, src0);
            const float e2 = __shfl_sync(FULLM, r0, src2);
            const float o2 = __shfl_sync(FULLM, r1, src2);
            const float e3 = __shfl_sync(FULLM, r2, src2);
            const float o3 = __shfl_sync(FULLM, r3, src2);
            split1(odd ? o0 : e0, ah[mt][0], al[mt][0]);
            split1(odd ? o1 : e1, ah[mt][1], al[mt][1]);
            split1(odd ? o2 : e2, ah[mt][2], al[mt][2]);
            split1(odd ? o3 : e3, ah[mt][3], al[mt][3]);
        }
#pragma unroll
        for (int nt = 0; nt < NT; nt++) {
            const int fidx = (NT == 4) ? (FOFF + kt * 4 + nt) : (FOFF + kt);
            const float4 B = *(const float4*)&swf[fidx * 128 + lane * 4];
            const uint32_t bh0 = __float_as_uint(B.x), bh1 = __float_as_uint(B.y);
            const uint32_t bl0 = __float_as_uint(B.z), bl1 = __float_as_uint(B.w);
#pragma unroll
            for (int mt = 0; mt < 2; mt++) {
                mma_tf32(Dn[mt][nt], ah[mt][0], ah[mt][1], ah[mt][2], ah[mt][3], bh0, bh1);
                mma_tf32(Dn[mt][nt], al[mt][0], al[mt][1], al[mt][2], al[mt][3], bh0, bh1);
                mma_tf32(Dn[mt][nt], ah[mt][0], ah[mt][1], ah[mt][2], ah[mt][3], bl0, bl1);
            }
        }
    }
}

// ---------------------------------------------------------------------------
// Fused gather (fp16 voxels, pipelined) + layers 2..4 on tensor cores.
// smem: [ wfrag 36*128 | bias 128 | svf 256*36 ] = 55,808 B
// ---------------------------------------------------------------------------
#define SMEM_FLOATS (36 * 128 + 128 + 256 * 36)
#define SMEM_BYTES  (SMEM_FLOATS * 4)

__global__ void __launch_bounds__(256, 2) fused_field_kernel(
    const float* __restrict__ coord,
    const float* __restrict__ b1g, const float* __restrict__ b2g,
    const float* __restrict__ b3g, const float* __restrict__ b4g,
    float* __restrict__ out)
{
    extern __shared__ float sm[];
    float* swf = sm;                      // 36*128
    float* sb  = sm + 36 * 128;           // 128
    float* svf = sm + 36 * 128 + 128;     // 256 * 36

    const int tid = threadIdx.x;
    {
        const float4* src = (const float4*)(g_wfrag + 16 * 128);
        float4* dst = (float4*)swf;
        for (int i = tid; i < 36 * 32; i += 256) dst[i] = src[i];
        if (tid < 32) {
            sb[tid]      = b1g[tid];
            sb[32 + tid] = b2g[tid];
            sb[64 + tid] = b3g[tid];
            sb[96 + tid] = (tid < 4) ? b4g[tid] : 0.0f;
        }
    }
    __syncthreads();

    const int warp  = tid >> 5;
    const int lane  = tid & 31;
    const int chunk = lane & 3;        // 16B slice of the 32 fp16 channels
    const int psub  = lane >> 2;       // point-of-8 in round

    // --- Phase 1: pipelined warp-cooperative gather of h1-pre -> svf ---
    // Load all 4 rounds' coordinates up front to break the per-round
    // coord -> address -> load dependence chain; fully unroll so ptxas
    // front-batches the corner LDGs across rounds (high MLP).
    float cr[4][3];
#pragma unroll
    for (int s = 0; s < 4; s++) {
        const int q   = (warp << 5) + (s << 3) + psub;
        const int pid = blockIdx.x * 256 + q;
        cr[s][0] = __ldg(&coord[pid * 3 + 0]);
        cr[s][1] = __ldg(&coord[pid * 3 + 1]);
        cr[s][2] = __ldg(&coord[pid * 3 + 2]);
    }

#pragma unroll
    for (int s = 0; s < 4; s++) {
        const int q = (warp << 5) + (s << 3) + psub;

        const float fx = (cr[s][0] + 1.0f) * 64.0f - 0.5f;
        const float fy = (cr[s][1] + 1.0f) * 64.0f - 0.5f;
        const float fz = (cr[s][2] + 1.0f) * 64.0f - 0.5f;

        const float x0f = floorf(fx), y0f = floorf(fy), z0f = floorf(fz);
        const float tx = fx - x0f, ty = fy - y0f, tz = fz - z0f;
        const int x0 = (int)x0f, y0 = (int)y0f, z0 = (int)z0f;

        int   xs[2], ys[2], zs[2];
        float wx[2], wy[2], wz[2];
        xs[0] = max(x0, 0);        xs[1] = min(x0 + 1, RES - 1);
        ys[0] = max(y0, 0);        ys[1] = min(y0 + 1, RES - 1);
        zs[0] = max(z0, 0);        zs[1] = min(z0 + 1, RES - 1);
        wx[0] = (x0 >= 0)          ? (1.0f - tx) : 0.0f;
        wx[1] = (x0 + 1 <= RES - 1)? tx          : 0.0f;
        wy[0] = (y0 >= 0)          ? (1.0f - ty) : 0.0f;
        wy[1] = (y0 + 1 <= RES - 1)? ty          : 0.0f;
        wz[0] = (z0 >= 0)          ? (1.0f - tz) : 0.0f;
        wz[1] = (z0 + 1 <= RES - 1)? tz          : 0.0f;

        // Batch all 8 corner loads before any consumption.
        uint4 raw[8];
        float w8[8];
#pragma unroll
        for (int c = 0; c < 8; c++) {
            const int kx = c & 1, ky = (c >> 1) & 1, kz = c >> 2;
            const int vox = ((zs[kz] * RES + ys[ky]) * RES + xs[kx]);
            raw[c] = __ldg(((const uint4*)(g_vox16 + ((size_t)vox << 5))) + chunk);
            w8[c]  = wz[kz] * wy[ky] * wx[kx];
        }

        float acc[8];
#pragma unroll
        for (int i = 0; i < 8; i++) acc[i] = 0.0f;
#pragma unroll
        for (int c = 0; c < 8; c++) {
            const __half2* h2 = (const __half2*)&raw[c];
            const float2 f0 = __half22float2(h2[0]);
            const float2 f1 = __half22float2(h2[1]);
            const float2 f2 = __half22float2(h2[2]);
            const float2 f3 = __half22float2(h2[3]);
            const float w = w8[c];
            acc[0] = fmaf(w, f0.x, acc[0]);  acc[1] = fmaf(w, f0.y, acc[1]);
            acc[2] = fmaf(w, f1.x, acc[2]);  acc[3] = fmaf(w, f1.y, acc[3]);
            acc[4] = fmaf(w, f2.x, acc[4]);  acc[5] = fmaf(w, f2.y, acc[5]);
            acc[6] = fmaf(w, f3.x, acc[6]);  acc[7] = fmaf(w, f3.y, acc[7]);
        }
        *(float4*)&svf[q * 36 + chunk * 8]     = make_float4(acc[0], acc[1], acc[2], acc[3]);
        *(float4*)&svf[q * 36 + chunk * 8 + 4] = make_float4(acc[4], acc[5], acc[6], acc[7]);
    }
    __syncwarp();

    // --- Phase 2: layers 2..4 on tensor cores (3xTF32) ---
    const int gq = lane >> 2, t = lane & 3;

    float bA[8];
#pragma unroll
    for (int kt = 0; kt < 4; kt++) {
        bA[2 * kt]     = sb[8 * kt + t];
        bA[2 * kt + 1] = sb[8 * kt + t + 4];
    }

    float D[2][4][4], Dn[2][4][4];

    // stage 1 (= layer 2): A = relu(svf + b1), W = W2, init b2
#pragma unroll
    for (int mt = 0; mt < 2; mt++)
#pragma unroll
        for (int nt = 0; nt < 4; nt++) {
            const float2 bb = *(const float2*)&sb[32 + 8 * nt + 2 * t];
            D[mt][nt][0] = bb.x; D[mt][nt][1] = bb.y;
            D[mt][nt][2] = bb.x; D[mt][nt][3] = bb.y;
        }
#pragma unroll
    for (int kt = 0; kt < 4; kt++) {
        uint32_t ah[2][4], al[2][4];
#pragma unroll
        for (int mt = 0; mt < 2; mt++) {
            const int q0 = warp * 32 + 16 * mt + gq;
            const float x0 = fmaxf(svf[q0 * 36 + 8 * kt + t]           + bA[2 * kt],     0.0f);
            const float x1 = fmaxf(svf[(q0 + 8) * 36 + 8 * kt + t]     + bA[2 * kt],     0.0f);
            const float x2 = fmaxf(svf[q0 * 36 + 8 * kt + t + 4]       + bA[2 * kt + 1], 0.0f);
            const float x3 = fmaxf(svf[(q0 + 8) * 36 + 8 * kt + t + 4] + bA[2 * kt + 1], 0.0f);
            split1(x0, ah[mt][0], al[mt][0]);
            split1(x1, ah[mt][1], al[mt][1]);
            split1(x2, ah[mt][2], al[mt][2]);
            split1(x3, ah[mt][3], al[mt][3]);
        }
#pragma unroll
        for (int nt = 0; nt < 4; nt++) {
            const float4 B = *(const float4*)&swf[(kt * 4 + nt) * 128 + lane * 4];
            const uint32_t bh0 = __float_as_uint(B.x), bh1 = __float_as_uint(B.y);
            const uint32_t bl0 = __float_as_uint(B.z), bl1 = __float_as_uint(B.w);
#pragma unroll
            for (int mt = 0; mt < 2; mt++) {
                mma_tf32(D[mt][nt], ah[mt][0], ah[mt][1], ah[mt][2], ah[mt][3], bh0, bh1);
                mma_tf32(D[mt][nt], al[mt][0], al[mt][1], al[mt][2], al[mt][3], bh0, bh1);
                mma_tf32(D[mt][nt], ah[mt][0], ah[mt][1], ah[mt][2], ah[mt][3], bl0, bl1);
            }
        }
    }
#pragma unroll
    for (int mt = 0; mt < 2; mt++)
#pragma unroll
        for (int nt = 0; nt < 4; nt++)
#pragma unroll
            for (int i = 0; i < 4; i++) D[mt][nt][i] = fmaxf(D[mt][nt][i], 0.0f);

    // stage 2 (= layer 3)
    mlp_stage_shfl<16, 64, 4>(D, Dn, swf, sb, lane);
#pragma unroll
    for (int mt = 0; mt < 2; mt++)
#pragma unroll
        for (int nt = 0; nt < 4; nt++)
#pragma unroll
            for (int i = 0; i < 4; i++) Dn[mt][nt][i] = fmaxf(Dn[mt][nt][i], 0.0f);

    // stage 3 (= layer 4), no relu
    mlp_stage_shfl<32, 96, 1>(Dn, D, swf, sb, lane);

    // store: rows g, g+8 of each m-tile, cols 2t, 2t+1 (valid cols < 4)
    if (t < 2) {
        const int base = blockIdx.x * 256 + warp * 32;
#pragma unroll
        for (int mt = 0; mt < 2; mt++) {
            const int p0 = base + 16 * mt + gq;
            *(float2*)&out[p0 * 4 + 2 * t]       = make_float2(D[mt][0][0], D[mt][0][1]);
            *(float2*)&out[(p0 + 8) * 4 + 2 * t] = make_float2(D[mt][0][2], D[mt][0][3]);
        }
    }
}

// ---------------------------------------------------------------------------
extern "C" void kernel_launch(void* const* d_in, const int* in_sizes, int n_in,
                              void* d_out, int out_size)
{
    const float* coord = (const float*)d_in[0];
    const float* grid  = (const float*)d_in[1];
    const float* w1 = (const float*)d_in[2];
    const float* b1 = (const float*)d_in[3];
    const float* w2 = (const float*)d_in[4];
    const float* b2 = (const float*)d_in[5];
    const float* w3 = (const float*)d_in[6];
    const float* b3 = (const float*)d_in[7];
    const float* w4 = (const float*)d_in[8];
    const float* b4 = (const float*)d_in[9];
    float* out = (float*)d_out;

    cudaFuncSetAttribute(fused_field_kernel,
                         cudaFuncAttributeMaxDynamicSharedMemorySize, SMEM_BYTES);

    prep_wfrag_kernel<<<52, 32>>>(w1, w2, w3, w4);
    voxel_w1_kernel<<<NVOX / 256, 256>>>(grid);
    fused_field_kernel<<<NPTS / 256, 256, SMEM_BYTES>>>(coord, b1, b2, b3, b4, out);
}

// round 8
// speedup vs baseline: 1.6663x; 1.1298x over previous
#include <cuda_runtime.h>
#include <cuda_fp16.h>
#include <cstdint>

#define RES   128
#define FEAT  32
#define NVOX  (RES * RES * RES)           // 2,097,152 voxels
#define NPTS  (2048 * 1024)               // 2,097,152 points
#define FULLM 0xffffffffu

// fp16 voxel tensor holding layer-1 pre-activations: vox[v*32+j] = (W1 @ g[:,v])[j]
__device__ __half g_vox16[(size_t)NVOX * FEAT];
// Split-tf32 W1 B-fragments (for the voxel transform kernel): 16 frags.
__device__ float g_wfrag[16 * 128];
// Split-fp16 B-fragments for W2 (0..7), W3 (8..15), W4 (16..17).
// Per lane: {hi_b0, hi_b1, lo_b0, lo_b1}.
__device__ uint4 g_whalf[18 * 32];

// ---------------------------------------------------------------------------
__device__ __forceinline__ void mma_tf32(float d[4],
                                         uint32_t a0, uint32_t a1, uint32_t a2, uint32_t a3,
                                         uint32_t b0, uint32_t b1) {
    asm volatile("mma.sync.aligned.m16n8k8.row.col.f32.tf32.tf32.f32 "
                 "{%0,%1,%2,%3}, {%4,%5,%6,%7}, {%8,%9}, {%0,%1,%2,%3};"
                 : "+f"(d[0]), "+f"(d[1]), "+f"(d[2]), "+f"(d[3])
                 : "r"(a0), "r"(a1), "r"(a2), "r"(a3), "r"(b0), "r"(b1));
}

__device__ __forceinline__ void mma_f16(float d[4],
                                        uint32_t a0, uint32_t a1, uint32_t a2, uint32_t a3,
                                        uint32_t b0, uint32_t b1) {
    asm volatile("mma.sync.aligned.m16n8k16.row.col.f32.f16.f16.f32 "
                 "{%0,%1,%2,%3}, {%4,%5,%6,%7}, {%8,%9}, {%0,%1,%2,%3};"
                 : "+f"(d[0]), "+f"(d[1]), "+f"(d[2]), "+f"(d[3])
                 : "r"(a0), "r"(a1), "r"(a2), "r"(a3), "r"(b0), "r"(b1));
}

__device__ __forceinline__ void split1(float x, uint32_t& h, uint32_t& l) {
    h = __float_as_uint(x) & 0xffffe000u;
    l = __float_as_uint(x - __uint_as_float(h));
}

// hi/lo fp16 split of a float pair (packed f16x2 each)
__device__ __forceinline__ void hilo2(float x, float y, uint32_t& hi, uint32_t& lo) {
    const __half2 h = __floats2half2_rn(x, y);
    hi = *(const uint32_t*)&h;
    const float2 hf = __half22float2(h);
    const __half2 l = __floats2half2_rn(x - hf.x, y - hf.y);
    lo = *(const uint32_t*)&l;
}

// relu, then hi/lo split
__device__ __forceinline__ void prelu_hilo2(float x, float y, uint32_t& hi, uint32_t& lo) {
    hilo2(fmaxf(x, 0.0f), fmaxf(y, 0.0f), hi, lo);
}

// ---------------------------------------------------------------------------
// Prep: split-tf32 W1 fragments (for voxel transform).
// ---------------------------------------------------------------------------
__global__ void prep_wfrag_kernel(const float* __restrict__ w1) {
    const int f = blockIdx.x;        // 0..15: kt*4 + nt
    const int lane = threadIdx.x;
    const int g = lane >> 2, t = lane & 3;
    const int kt = f >> 2, nt = f & 3;
    const float b0 = w1[(8 * nt + g) * 32 + 8 * kt + t];
    const float b1 = w1[(8 * nt + g) * 32 + 8 * kt + t + 4];
    const uint32_t h0 = __float_as_uint(b0) & 0xffffe000u;
    const uint32_t h1 = __float_as_uint(b1) & 0xffffe000u;
    float4 v;
    v.x = __uint_as_float(h0);
    v.y = __uint_as_float(h1);
    v.z = b0 - v.x;
    v.w = b1 - v.y;
    *(float4*)&g_wfrag[f * 128 + lane * 4] = v;
}

// ---------------------------------------------------------------------------
// Prep: split-fp16 B-fragments for W2/W3/W4 in m16n8k16 lane order.
// b0 = (k=2t,2t+1, n=g), b1 = (k=2t+8,2t+9, n=g), per 16-wide k-step.
// ---------------------------------------------------------------------------
__global__ void prep_whalf_kernel(const float* __restrict__ w2,
                                  const float* __restrict__ w3,
                                  const float* __restrict__ w4) {
    const int f = blockIdx.x;        // 0..17
    const int lane = threadIdx.x;
    const int g = lane >> 2, t = lane & 3;
    float v0 = 0.f, v1 = 0.f, v2 = 0.f, v3 = 0.f;
    if (f < 16) {
        const float* W = (f < 8) ? w2 : w3;
        const int r = f & 7, ks = r >> 2, nt = r & 3;
        const int row = 8 * nt + g, k = 16 * ks;
        v0 = W[row * 32 + k + 2 * t];
        v1 = W[row * 32 + k + 2 * t + 1];
        v2 = W[row * 32 + k + 2 * t + 8];
        v3 = W[row * 32 + k + 2 * t + 9];
    } else {
        const int ks = f - 16;
        if (g < 4) {
            v0 = w4[g * 32 + 16 * ks + 2 * t];
            v1 = w4[g * 32 + 16 * ks + 2 * t + 1];
            v2 = w4[g * 32 + 16 * ks + 2 * t + 8];
            v3 = w4[g * 32 + 16 * ks + 2 * t + 9];
        }
    }
    uint4 u;
    hilo2(v0, v1, u.x, u.z);
    hilo2(v2, v3, u.y, u.w);
    g_whalf[f * 32 + lane] = u;
}

// ---------------------------------------------------------------------------
// Voxel transform: grid (C,D,H,W) -> fp16 (D*H*W, 32) of W1 @ v (3xTF32).
// ---------------------------------------------------------------------------
#define TC_STRIDE 264
__global__ void __launch_bounds__(256) voxel_w1_kernel(const float* __restrict__ g) {
    __shared__ float tile[32 * TC_STRIDE];
    __shared__ float swf[16 * 128];
    const int tid = threadIdx.x;
    const int v0 = blockIdx.x * 256;

    {
        const float4* src = (const float4*)g_wfrag;
        float4* dst = (float4*)swf;
        for (int i = tid; i < 16 * 32; i += 256) dst[i] = src[i];
    }
#pragma unroll
    for (int c = 0; c < 32; c++)
        tile[c * TC_STRIDE + tid] = g[(size_t)c * NVOX + v0 + tid];
    __syncthreads();

    const int warp = tid >> 5, lane = tid & 31;
    const int gq = lane >> 2, t = lane & 3;
    const int vb = warp * 32;

    float D[2][4][4];
#pragma unroll
    for (int mt = 0; mt < 2; mt++)
#pragma unroll
        for (int nt = 0; nt < 4; nt++)
#pragma unroll
            for (int i = 0; i < 4; i++) D[mt][nt][i] = 0.0f;

#pragma unroll
    for (int kt = 0; kt < 4; kt++) {
        uint32_t ah[2][4], al[2][4];
#pragma unroll
        for (int mt = 0; mt < 2; mt++) {
            const int r = vb + 16 * mt + gq;
            split1(tile[(8 * kt + t) * TC_STRIDE + r],         ah[mt][0], al[mt][0]);
            split1(tile[(8 * kt + t) * TC_STRIDE + r + 8],     ah[mt][1], al[mt][1]);
            split1(tile[(8 * kt + t + 4) * TC_STRIDE + r],     ah[mt][2], al[mt][2]);
            split1(tile[(8 * kt + t + 4) * TC_STRIDE + r + 8], ah[mt][3], al[mt][3]);
        }
#pragma unroll
        for (int nt = 0; nt < 4; nt++) {
            const float4 B = *(const float4*)&swf[(kt * 4 + nt) * 128 + lane * 4];
            const uint32_t bh0 = __float_as_uint(B.x), bh1 = __float_as_uint(B.y);
            const uint32_t bl0 = __float_as_uint(B.z), bl1 = __float_as_uint(B.w);
#pragma unroll
            for (int mt = 0; mt < 2; mt++) {
                mma_tf32(D[mt][nt], ah[mt][0], ah[mt][1], ah[mt][2], ah[mt][3], bh0, bh1);
                mma_tf32(D[mt][nt], al[mt][0], al[mt][1], al[mt][2], al[mt][3], bh0, bh1);
                mma_tf32(D[mt][nt], ah[mt][0], ah[mt][1], ah[mt][2], ah[mt][3], bl0, bl1);
            }
        }
    }
#pragma unroll
    for (int mt = 0; mt < 2; mt++)
#pragma unroll
        for (int nt = 0; nt < 4; nt++) {
            const int v = v0 + vb + 16 * mt + gq;
            const __half2 p0 = __floats2half2_rn(D[mt][nt][0], D[mt][nt][1]);
            const __half2 p1 = __floats2half2_rn(D[mt][nt][2], D[mt][nt][3]);
            *(__half2*)&g_vox16[(size_t)v * 32 + 8 * nt + 2 * t]       = p0;
            *(__half2*)&g_vox16[(size_t)(v + 8) * 32 + 8 * nt + 2 * t] = p1;
        }
}

// ---------------------------------------------------------------------------
// Fused gather + 3 MLP layers on fp16 mma with hi/lo operand splitting.
// No shuffles: fp16 A-frag layout == fp32 D layout of adjacent n-tile pair.
// Activations stored as hi[16] + lo[16] uints per point (stride 36 — the
// A-frag LDS.32 pattern remains a perfect bank permutation).
// 3-term mma: Ahi*Bhi + Alo*Bhi + Ahi*Blo  (fp32-class precision per layer).
// ---------------------------------------------------------------------------
#define SV_STRIDE 36   // uints per point: 16 hi + 16 lo + 4 pad

__global__ void __launch_bounds__(256, 2) fused_field_kernel(
    const float* __restrict__ coord,
    const float* __restrict__ b1g, const float* __restrict__ b2g,
    const float* __restrict__ b3g, const float* __restrict__ b4g,
    float* __restrict__ out)
{
    __shared__ uint4 swh[18 * 32];             //  9,216 B
    __shared__ float sb[128];                  //    512 B
    __shared__ uint32_t svu[256 * SV_STRIDE];  // 36,864 B   (total 46,592 B)

    const int tid = threadIdx.x;
    {
        for (int i = tid; i < 18 * 32; i += 256) swh[i] = g_whalf[i];
        if (tid < 32) {
            sb[tid]      = b1g[tid];
            sb[32 + tid] = b2g[tid];
            sb[64 + tid] = b3g[tid];
            sb[96 + tid] = (tid < 4) ? b4g[tid] : 0.0f;
        }
    }
    __syncthreads();

    const int warp  = tid >> 5;
    const int lane  = tid & 31;
    const int chunk = lane & 3;        // 16B slice (8 channels) of 32 fp16 channels
    const int psub  = lane >> 2;       // point-of-8 in round

    // --- Phase 1: pipelined warp-cooperative gather -> split fp16 in svu ---
    float cr[4][3];
#pragma unroll
    for (int s = 0; s < 4; s++) {
        const int q   = (warp << 5) + (s << 3) + psub;
        const int pid = blockIdx.x * 256 + q;
        cr[s][0] = __ldg(&coord[pid * 3 + 0]);
        cr[s][1] = __ldg(&coord[pid * 3 + 1]);
        cr[s][2] = __ldg(&coord[pid * 3 + 2]);
    }

    float bb[8];
#pragma unroll
    for (int i = 0; i < 8; i++) bb[i] = sb[8 * chunk + i];   // b1 slice

#pragma unroll
    for (int s = 0; s < 4; s++) {
        const int q = (warp << 5) + (s << 3) + psub;

        const float fx = (cr[s][0] + 1.0f) * 64.0f - 0.5f;
        const float fy = (cr[s][1] + 1.0f) * 64.0f - 0.5f;
        const float fz = (cr[s][2] + 1.0f) * 64.0f - 0.5f;

        const float x0f = floorf(fx), y0f = floorf(fy), z0f = floorf(fz);
        const float tx = fx - x0f, ty = fy - y0f, tz = fz - z0f;
        const int x0 = (int)x0f, y0 = (int)y0f, z0 = (int)z0f;

        int   xs[2], ys[2], zs[2];
        float wx[2], wy[2], wz[2];
        xs[0] = max(x0, 0);        xs[1] = min(x0 + 1, RES - 1);
        ys[0] = max(y0, 0);        ys[1] = min(y0 + 1, RES - 1);
        zs[0] = max(z0, 0);        zs[1] = min(z0 + 1, RES - 1);
        wx[0] = (x0 >= 0)          ? (1.0f - tx) : 0.0f;
        wx[1] = (x0 + 1 <= RES - 1)? tx          : 0.0f;
        wy[0] = (y0 >= 0)          ? (1.0f - ty) : 0.0f;
        wy[1] = (y0 + 1 <= RES - 1)? ty          : 0.0f;
        wz[0] = (z0 >= 0)          ? (1.0f - tz) : 0.0f;
        wz[1] = (z0 + 1 <= RES - 1)? tz          : 0.0f;

        uint4 raw[8];
        float w8[8];
#pragma unroll
        for (int c = 0; c < 8; c++) {
            const int kx = c & 1, ky = (c >> 1) & 1, kz = c >> 2;
            const int vox = ((zs[kz] * RES + ys[ky]) * RES + xs[kx]);
            raw[c] = __ldg(((const uint4*)(g_vox16 + ((size_t)vox << 5))) + chunk);
            w8[c]  = wz[kz] * wy[ky] * wx[kx];
        }

        float acc[8];
#pragma unroll
        for (int i = 0; i < 8; i++) acc[i] = bb[i];          // bias folded in
#pragma unroll
        for (int c = 0; c < 8; c++) {
            const __half2* h2 = (const __half2*)&raw[c];
            const float2 f0 = __half22float2(h2[0]);
            const float2 f1 = __half22float2(h2[1]);
            const float2 f2 = __half22float2(h2[2]);
            const float2 f3 = __half22float2(h2[3]);
            const float w = w8[c];
            acc[0] = fmaf(w, f0.x, acc[0]);  acc[1] = fmaf(w, f0.y, acc[1]);
            acc[2] = fmaf(w, f1.x, acc[2]);  acc[3] = fmaf(w, f1.y, acc[3]);
            acc[4] = fmaf(w, f2.x, acc[4]);  acc[5] = fmaf(w, f2.y, acc[5]);
            acc[6] = fmaf(w, f3.x, acc[6]);  acc[7] = fmaf(w, f3.y, acc[7]);
        }
        uint4 hi, lo;
        prelu_hilo2(acc[0], acc[1], hi.x, lo.x);
        prelu_hilo2(acc[2], acc[3], hi.y, lo.y);
        prelu_hilo2(acc[4], acc[5], hi.z, lo.z);
        prelu_hilo2(acc[6], acc[7], hi.w, lo.w);
        *(uint4*)&svu[q * SV_STRIDE + 4 * chunk]      = hi;  // relu(h1) hi
        *(uint4*)&svu[q * SV_STRIDE + 16 + 4 * chunk] = lo;  // relu(h1) lo
    }
    __syncwarp();

    // --- Phase 2: layers 2..4 on fp16 tensor cores, 3-term split mma ---
    const int gq = lane >> 2, t = lane & 3;

    float D[2][4][4], Dn[2][4][4];

    // layer 2: A = svu hi/lo, B = W2 frags 0..7, init b2
#pragma unroll
    for (int mt = 0; mt < 2; mt++)
#pragma unroll
        for (int nt = 0; nt < 4; nt++) {
            const float2 b2v = *(const float2*)&sb[32 + 8 * nt + 2 * t];
            D[mt][nt][0] = b2v.x; D[mt][nt][1] = b2v.y;
            D[mt][nt][2] = b2v.x; D[mt][nt][3] = b2v.y;
        }
#pragma unroll
    for (int mt = 0; mt < 2; mt++) {
        const int q0 = warp * 32 + 16 * mt + gq;
#pragma unroll
        for (int ks = 0; ks < 2; ks++) {
            const uint32_t a0h = svu[q0 * SV_STRIDE + 8 * ks + t];
            const uint32_t a1h = svu[(q0 + 8) * SV_STRIDE + 8 * ks + t];
            const uint32_t a2h = svu[q0 * SV_STRIDE + 8 * ks + t + 4];
            const uint32_t a3h = svu[(q0 + 8) * SV_STRIDE + 8 * ks + t + 4];
            const uint32_t a0l = svu[q0 * SV_STRIDE + 16 + 8 * ks + t];
            const uint32_t a1l = svu[(q0 + 8) * SV_STRIDE + 16 + 8 * ks + t];
            const uint32_t a2l = svu[q0 * SV_STRIDE + 16 + 8 * ks + t + 4];
            const uint32_t a3l = svu[(q0 + 8) * SV_STRIDE + 16 + 8 * ks + t + 4];
#pragma unroll
            for (int nt = 0; nt < 4; nt++) {
                const uint4 B = swh[(ks * 4 + nt) * 32 + lane];
                mma_f16(D[mt][nt], a0h, a1h, a2h, a3h, B.x, B.y);
                mma_f16(D[mt][nt], a0l, a1l, a2l, a3l, B.x, B.y);
                mma_f16(D[mt][nt], a0h, a1h, a2h, a3h, B.z, B.w);
            }
        }
    }

    // layer 3: A = relu(D) hi/lo, B = W3 frags 8..15, init b3
#pragma unroll
    for (int mt = 0; mt < 2; mt++)
#pragma unroll
        for (int nt = 0; nt < 4; nt++) {
            const float2 b3v = *(const float2*)&sb[64 + 8 * nt + 2 * t];
            Dn[mt][nt][0] = b3v.x; Dn[mt][nt][1] = b3v.y;
            Dn[mt][nt][2] = b3v.x; Dn[mt][nt][3] = b3v.y;
        }
#pragma unroll
    for (int mt = 0; mt < 2; mt++) {
#pragma unroll
        for (int ks = 0; ks < 2; ks++) {
            uint32_t a0h, a1h, a2h, a3h, a0l, a1l, a2l, a3l;
            prelu_hilo2(D[mt][2 * ks][0],     D[mt][2 * ks][1],     a0h, a0l);
            prelu_hilo2(D[mt][2 * ks][2],     D[mt][2 * ks][3],     a1h, a1l);
            prelu_hilo2(D[mt][2 * ks + 1][0], D[mt][2 * ks + 1][1], a2h, a2l);
            prelu_hilo2(D[mt][2 * ks + 1][2], D[mt][2 * ks + 1][3], a3h, a3l);
#pragma unroll
            for (int nt = 0; nt < 4; nt++) {
                const uint4 B = swh[(8 + ks * 4 + nt) * 32 + lane];
                mma_f16(Dn[mt][nt], a0h, a1h, a2h, a3h, B.x, B.y);
                mma_f16(Dn[mt][nt], a0l, a1l, a2l, a3l, B.x, B.y);
                mma_f16(Dn[mt][nt], a0h, a1h, a2h, a3h, B.z, B.w);
            }
        }
    }

    // layer 4: A = relu(Dn) hi/lo, B = W4 frags 16..17, init b4, no relu out
    float O[2][4];
#pragma unroll
    for (int mt = 0; mt < 2; mt++) {
        const float2 b4v = *(const float2*)&sb[96 + 2 * t];
        O[mt][0] = b4v.x; O[mt][1] = b4v.y;
        O[mt][2] = b4v.x; O[mt][3] = b4v.y;
    }
#pragma unroll
    for (int mt = 0; mt < 2; mt++) {
#pragma unroll
        for (int ks = 0; ks < 2; ks++) {
            uint32_t a0h, a1h, a2h, a3h, a0l, a1l, a2l, a3l;
            prelu_hilo2(Dn[mt][2 * ks][0],     Dn[mt][2 * ks][1],     a0h, a0l);
            prelu_hilo2(Dn[mt][2 * ks][2],     Dn[mt][2 * ks][3],     a1h, a1l);
            prelu_hilo2(Dn[mt][2 * ks + 1][0], Dn[mt][2 * ks + 1][1], a2h, a2l);
            prelu_hilo2(Dn[mt][2 * ks + 1][2], Dn[mt][2 * ks + 1][3], a3h, a3l);
            const uint4 B = swh[(16 + ks) * 32 + lane];
            mma_f16(O[mt], a0h, a1h, a2h, a3h, B.x, B.y);
            mma_f16(O[mt], a0l, a1l, a2l, a3l, B.x, B.y);
            mma_f16(O[mt], a0h, a1h, a2h, a3h, B.z, B.w);
        }
    }

    // store: rows g, g+8 of each m-tile, cols 2t,2t+1 (valid cols < 4)
    if (t < 2) {
        const int base = blockIdx.x * 256 + warp * 32;
#pragma unroll
        for (int mt = 0; mt < 2; mt++) {
            const int p0 = base + 16 * mt + gq;
            *(float2*)&out[p0 * 4 + 2 * t]       = make_float2(O[mt][0], O[mt][1]);
            *(float2*)&out[(p0 + 8) * 4 + 2 * t] = make_float2(O[mt][2], O[mt][3]);
        }
    }
}

// ---------------------------------------------------------------------------
extern "C" void kernel_launch(void* const* d_in, const int* in_sizes, int n_in,
                              void* d_out, int out_size)
{
    const float* coord = (const float*)d_in[0];
    const float* grid  = (const float*)d_in[1];
    const float* w1 = (const float*)d_in[2];
    const float* b1 = (const float*)d_in[3];
    const float* w2 = (const float*)d_in[4];
    const float* b2 = (const float*)d_in[5];
    const float* w3 = (const float*)d_in[6];
    const float* b3 = (const float*)d_in[7];
    const float* w4 = (const float*)d_in[8];
    const float* b4 = (const float*)d_in[9];
    float* out = (float*)d_out;

    prep_wfrag_kernel<<<16, 32>>>(w1);
    prep_whalf_kernel<<<18, 32>>>(w2, w3, w4);
    voxel_w1_kernel<<<NVOX / 256, 256>>>(grid);
    fused_field_kernel<<<NPTS / 256, 256>>>(coord, b1, b2, b3, b4, out);
}

// round 9
// speedup vs baseline: 1.8064x; 1.0841x over previous
#include <cuda_runtime.h>
#include <cuda_fp16.h>
#include <cstdint>

#define RES   128
#define FEAT  32
#define NVOX  (RES * RES * RES)           // 2,097,152 voxels
#define NPTS  (2048 * 1024)               // 2,097,152 points
#define FULLM 0xffffffffu

// fp16 voxel tensor holding layer-1 pre-activations: vox[v*32+j] = (W1 @ g[:,v])[j]
__device__ __half g_vox16[(size_t)NVOX * FEAT];
// Split-tf32 W1 B-fragments (for the voxel transform kernel): 16 frags.
__device__ float g_wfrag[16 * 128];
// Split-fp16 B-fragments for W2 (0..7), W3 (8..15), W4 (16..17).
// Per lane: {hi_b0, hi_b1, lo_b0, lo_b1}.
__device__ uint4 g_whalf[18 * 32];

// ---------------------------------------------------------------------------
__device__ __forceinline__ void mma_tf32(float d[4],
                                         uint32_t a0, uint32_t a1, uint32_t a2, uint32_t a3,
                                         uint32_t b0, uint32_t b1) {
    asm volatile("mma.sync.aligned.m16n8k8.row.col.f32.tf32.tf32.f32 "
                 "{%0,%1,%2,%3}, {%4,%5,%6,%7}, {%8,%9}, {%0,%1,%2,%3};"
                 : "+f"(d[0]), "+f"(d[1]), "+f"(d[2]), "+f"(d[3])
                 : "r"(a0), "r"(a1), "r"(a2), "r"(a3), "r"(b0), "r"(b1));
}

__device__ __forceinline__ void mma_f16(float d[4],
                                        uint32_t a0, uint32_t a1, uint32_t a2, uint32_t a3,
                                        uint32_t b0, uint32_t b1) {
    asm volatile("mma.sync.aligned.m16n8k16.row.col.f32.f16.f16.f32 "
                 "{%0,%1,%2,%3}, {%4,%5,%6,%7}, {%8,%9}, {%0,%1,%2,%3};"
                 : "+f"(d[0]), "+f"(d[1]), "+f"(d[2]), "+f"(d[3])
                 : "r"(a0), "r"(a1), "r"(a2), "r"(a3), "r"(b0), "r"(b1));
}

__device__ __forceinline__ void split1(float x, uint32_t& h, uint32_t& l) {
    h = __float_as_uint(x) & 0xffffe000u;
    l = __float_as_uint(x - __uint_as_float(h));
}

// hi/lo fp16 split of a float pair (packed f16x2 each)
__device__ __forceinline__ void hilo2(float x, float y, uint32_t& hi, uint32_t& lo) {
    const __half2 h = __floats2half2_rn(x, y);
    hi = *(const uint32_t*)&h;
    const float2 hf = __half22float2(h);
    const __half2 l = __floats2half2_rn(x - hf.x, y - hf.y);
    lo = *(const uint32_t*)&l;
}

// relu, then hi/lo split
__device__ __forceinline__ void prelu_hilo2(float x, float y, uint32_t& hi, uint32_t& lo) {
    hilo2(fmaxf(x, 0.0f), fmaxf(y, 0.0f), hi, lo);
}

// ---------------------------------------------------------------------------
// Prep: split-tf32 W1 fragments (for voxel transform).
// ---------------------------------------------------------------------------
__global__ void prep_wfrag_kernel(const float* __restrict__ w1) {
    const int f = blockIdx.x;        // 0..15: kt*4 + nt
    const int lane = threadIdx.x;
    const int g = lane >> 2, t = lane & 3;
    const int kt = f >> 2, nt = f & 3;
    const float b0 = w1[(8 * nt + g) * 32 + 8 * kt + t];
    const float b1 = w1[(8 * nt + g) * 32 + 8 * kt + t + 4];
    const uint32_t h0 = __float_as_uint(b0) & 0xffffe000u;
    const uint32_t h1 = __float_as_uint(b1) & 0xffffe000u;
    float4 v;
    v.x = __uint_as_float(h0);
    v.y = __uint_as_float(h1);
    v.z = b0 - v.x;
    v.w = b1 - v.y;
    *(float4*)&g_wfrag[f * 128 + lane * 4] = v;
}

// ---------------------------------------------------------------------------
// Prep: split-fp16 B-fragments for W2/W3/W4 in m16n8k16 lane order.
// ---------------------------------------------------------------------------
__global__ void prep_whalf_kernel(const float* __restrict__ w2,
                                  const float* __restrict__ w3,
                                  const float* __restrict__ w4) {
    const int f = blockIdx.x;        // 0..17
    const int lane = threadIdx.x;
    const int g = lane >> 2, t = lane & 3;
    float v0 = 0.f, v1 = 0.f, v2 = 0.f, v3 = 0.f;
    if (f < 16) {
        const float* W = (f < 8) ? w2 : w3;
        const int r = f & 7, ks = r >> 2, nt = r & 3;
        const int row = 8 * nt + g, k = 16 * ks;
        v0 = W[row * 32 + k + 2 * t];
        v1 = W[row * 32 + k + 2 * t + 1];
        v2 = W[row * 32 + k + 2 * t + 8];
        v3 = W[row * 32 + k + 2 * t + 9];
    } else {
        const int ks = f - 16;
        if (g < 4) {
            v0 = w4[g * 32 + 16 * ks + 2 * t];
            v1 = w4[g * 32 + 16 * ks + 2 * t + 1];
            v2 = w4[g * 32 + 16 * ks + 2 * t + 8];
            v3 = w4[g * 32 + 16 * ks + 2 * t + 9];
        }
    }
    uint4 u;
    hilo2(v0, v1, u.x, u.z);
    hilo2(v2, v3, u.y, u.w);
    g_whalf[f * 32 + lane] = u;
}

// ---------------------------------------------------------------------------
// Voxel transform: grid (C,D,H,W) -> fp16 (D*H*W, 32) of W1 @ v (3xTF32).
// ---------------------------------------------------------------------------
#define TC_STRIDE 264
__global__ void __launch_bounds__(256) voxel_w1_kernel(const float* __restrict__ g) {
    __shared__ float tile[32 * TC_STRIDE];
    __shared__ float swf[16 * 128];
    const int tid = threadIdx.x;
    const int v0 = blockIdx.x * 256;

    {
        const float4* src = (const float4*)g_wfrag;
        float4* dst = (float4*)swf;
        for (int i = tid; i < 16 * 32; i += 256) dst[i] = src[i];
    }
#pragma unroll
    for (int c = 0; c < 32; c++)
        tile[c * TC_STRIDE + tid] = g[(size_t)c * NVOX + v0 + tid];
    __syncthreads();

    const int warp = tid >> 5, lane = tid & 31;
    const int gq = lane >> 2, t = lane & 3;
    const int vb = warp * 32;

    float D[2][4][4];
#pragma unroll
    for (int mt = 0; mt < 2; mt++)
#pragma unroll
        for (int nt = 0; nt < 4; nt++)
#pragma unroll
            for (int i = 0; i < 4; i++) D[mt][nt][i] = 0.0f;

#pragma unroll
    for (int kt = 0; kt < 4; kt++) {
        uint32_t ah[2][4], al[2][4];
#pragma unroll
        for (int mt = 0; mt < 2; mt++) {
            const int r = vb + 16 * mt + gq;
            split1(tile[(8 * kt + t) * TC_STRIDE + r],         ah[mt][0], al[mt][0]);
            split1(tile[(8 * kt + t) * TC_STRIDE + r + 8],     ah[mt][1], al[mt][1]);
            split1(tile[(8 * kt + t + 4) * TC_STRIDE + r],     ah[mt][2], al[mt][2]);
            split1(tile[(8 * kt + t + 4) * TC_STRIDE + r + 8], ah[mt][3], al[mt][3]);
        }
#pragma unroll
        for (int nt = 0; nt < 4; nt++) {
            const float4 B = *(const float4*)&swf[(kt * 4 + nt) * 128 + lane * 4];
            const uint32_t bh0 = __float_as_uint(B.x), bh1 = __float_as_uint(B.y);
            const uint32_t bl0 = __float_as_uint(B.z), bl1 = __float_as_uint(B.w);
#pragma unroll
            for (int mt = 0; mt < 2; mt++) {
                mma_tf32(D[mt][nt], ah[mt][0], ah[mt][1], ah[mt][2], ah[mt][3], bh0, bh1);
                mma_tf32(D[mt][nt], al[mt][0], al[mt][1], al[mt][2], al[mt][3], bh0, bh1);
                mma_tf32(D[mt][nt], ah[mt][0], ah[mt][1], ah[mt][2], ah[mt][3], bl0, bl1);
            }
        }
    }
#pragma unroll
    for (int mt = 0; mt < 2; mt++)
#pragma unroll
        for (int nt = 0; nt < 4; nt++) {
            const int v = v0 + vb + 16 * mt + gq;
            const __half2 p0 = __floats2half2_rn(D[mt][nt][0], D[mt][nt][1]);
            const __half2 p1 = __floats2half2_rn(D[mt][nt][2], D[mt][nt][3]);
            *(__half2*)&g_vox16[(size_t)v * 32 + 8 * nt + 2 * t]       = p0;
            *(__half2*)&g_vox16[(size_t)(v + 8) * 32 + 8 * nt + 2 * t] = p1;
        }
}

// ---------------------------------------------------------------------------
// Fused gather + 3 MLP layers (fp16 mma, hi/lo split operands).
// Phase 2 restructured: the two m-tiles run the full layer chain
// SEQUENTIALLY, halving live accumulators (64 -> 32 fp regs) so the kernel
// fits 3 blocks/SM (__launch_bounds__(256,3), 85-reg cap) -> 24 warps/SM.
// ---------------------------------------------------------------------------
#define SV_STRIDE 36   // uints per point: 16 hi + 16 lo + 4 pad

__global__ void __launch_bounds__(256, 3) fused_field_kernel(
    const float* __restrict__ coord,
    const float* __restrict__ b1g, const float* __restrict__ b2g,
    const float* __restrict__ b3g, const float* __restrict__ b4g,
    float* __restrict__ out)
{
    __shared__ uint4 swh[18 * 32];             //  9,216 B
    __shared__ float sb[128];                  //    512 B
    __shared__ uint32_t svu[256 * SV_STRIDE];  // 36,864 B   (total 46,592 B)

    const int tid = threadIdx.x;
    {
        for (int i = tid; i < 18 * 32; i += 256) swh[i] = g_whalf[i];
        if (tid < 32) {
            sb[tid]      = b1g[tid];
            sb[32 + tid] = b2g[tid];
            sb[64 + tid] = b3g[tid];
            sb[96 + tid] = (tid < 4) ? b4g[tid] : 0.0f;
        }
    }
    __syncthreads();

    const int warp  = tid >> 5;
    const int lane  = tid & 31;
    const int chunk = lane & 3;        // 16B slice (8 channels) of 32 fp16 channels
    const int psub  = lane >> 2;       // point-of-8 in round

    // --- Phase 1: pipelined warp-cooperative gather -> split fp16 in svu ---
    float cr[4][3];
#pragma unroll
    for (int s = 0; s < 4; s++) {
        const int q   = (warp << 5) + (s << 3) + psub;
        const int pid = blockIdx.x * 256 + q;
        cr[s][0] = __ldg(&coord[pid * 3 + 0]);
        cr[s][1] = __ldg(&coord[pid * 3 + 1]);
        cr[s][2] = __ldg(&coord[pid * 3 + 2]);
    }

    float bb[8];
#pragma unroll
    for (int i = 0; i < 8; i++) bb[i] = sb[8 * chunk + i];   // b1 slice

#pragma unroll
    for (int s = 0; s < 4; s++) {
        const int q = (warp << 5) + (s << 3) + psub;

        const float fx = (cr[s][0] + 1.0f) * 64.0f - 0.5f;
        const float fy = (cr[s][1] + 1.0f) * 64.0f - 0.5f;
        const float fz = (cr[s][2] + 1.0f) * 64.0f - 0.5f;

        const float x0f = floorf(fx), y0f = floorf(fy), z0f = floorf(fz);
        const float tx = fx - x0f, ty = fy - y0f, tz = fz - z0f;
        const int x0 = (int)x0f, y0 = (int)y0f, z0 = (int)z0f;

        int   xs[2], ys[2], zs[2];
        float wx[2], wy[2], wz[2];
        xs[0] = max(x0, 0);        xs[1] = min(x0 + 1, RES - 1);
        ys[0] = max(y0, 0);        ys[1] = min(y0 + 1, RES - 1);
        zs[0] = max(z0, 0);        zs[1] = min(z0 + 1, RES - 1);
        wx[0] = (x0 >= 0)          ? (1.0f - tx) : 0.0f;
        wx[1] = (x0 + 1 <= RES - 1)? tx          : 0.0f;
        wy[0] = (y0 >= 0)          ? (1.0f - ty) : 0.0f;
        wy[1] = (y0 + 1 <= RES - 1)? ty          : 0.0f;
        wz[0] = (z0 >= 0)          ? (1.0f - tz) : 0.0f;
        wz[1] = (z0 + 1 <= RES - 1)? tz          : 0.0f;

        uint4 raw[8];
        float w8[8];
#pragma unroll
        for (int c = 0; c < 8; c++) {
            const int kx = c & 1, ky = (c >> 1) & 1, kz = c >> 2;
            const int vox = ((zs[kz] * RES + ys[ky]) * RES + xs[kx]);
            raw[c] = __ldg(((const uint4*)(g_vox16 + ((size_t)vox << 5))) + chunk);
            w8[c]  = wz[kz] * wy[ky] * wx[kx];
        }

        float acc[8];
#pragma unroll
        for (int i = 0; i < 8; i++) acc[i] = bb[i];          // bias folded in
#pragma unroll
        for (int c = 0; c < 8; c++) {
            const __half2* h2 = (const __half2*)&raw[c];
            const float2 f0 = __half22float2(h2[0]);
            const float2 f1 = __half22float2(h2[1]);
            const float2 f2 = __half22float2(h2[2]);
            const float2 f3 = __half22float2(h2[3]);
            const float w = w8[c];
            acc[0] = fmaf(w, f0.x, acc[0]);  acc[1] = fmaf(w, f0.y, acc[1]);
            acc[2] = fmaf(w, f1.x, acc[2]);  acc[3] = fmaf(w, f1.y, acc[3]);
            acc[4] = fmaf(w, f2.x, acc[4]);  acc[5] = fmaf(w, f2.y, acc[5]);
            acc[6] = fmaf(w, f3.x, acc[6]);  acc[7] = fmaf(w, f3.y, acc[7]);
        }
        uint4 hi, lo;
        prelu_hilo2(acc[0], acc[1], hi.x, lo.x);
        prelu_hilo2(acc[2], acc[3], hi.y, lo.y);
        prelu_hilo2(acc[4], acc[5], hi.z, lo.z);
        prelu_hilo2(acc[6], acc[7], hi.w, lo.w);
        *(uint4*)&svu[q * SV_STRIDE + 4 * chunk]      = hi;  // relu(h1) hi
        *(uint4*)&svu[q * SV_STRIDE + 16 + 4 * chunk] = lo;  // relu(h1) lo
    }
    __syncwarp();

    // --- Phase 2: layers 2..4, one m-tile at a time (halved reg pressure) ---
    const int gq = lane >> 2, t = lane & 3;

#pragma unroll
    for (int mt = 0; mt < 2; mt++) {
        const int q0 = warp * 32 + 16 * mt + gq;

        // layer 2: A = svu hi/lo, B = W2 frags 0..7, init b2
        float D[4][4];
#pragma unroll
        for (int nt = 0; nt < 4; nt++) {
            const float2 b2v = *(const float2*)&sb[32 + 8 * nt + 2 * t];
            D[nt][0] = b2v.x; D[nt][1] = b2v.y;
            D[nt][2] = b2v.x; D[nt][3] = b2v.y;
        }
#pragma unroll
        for (int ks = 0; ks < 2; ks++) {
            const uint32_t a0h = svu[q0 * SV_STRIDE + 8 * ks + t];
            const uint32_t a1h = svu[(q0 + 8) * SV_STRIDE + 8 * ks + t];
            const uint32_t a2h = svu[q0 * SV_STRIDE + 8 * ks + t + 4];
            const uint32_t a3h = svu[(q0 + 8) * SV_STRIDE + 8 * ks + t + 4];
            const uint32_t a0l = svu[q0 * SV_STRIDE + 16 + 8 * ks + t];
            const uint32_t a1l = svu[(q0 + 8) * SV_STRIDE + 16 + 8 * ks + t];
            const uint32_t a2l = svu[q0 * SV_STRIDE + 16 + 8 * ks + t + 4];
            const uint32_t a3l = svu[(q0 + 8) * SV_STRIDE + 16 + 8 * ks + t + 4];
#pragma unroll
            for (int nt = 0; nt < 4; nt++) {
                const uint4 B = swh[(ks * 4 + nt) * 32 + lane];
                mma_f16(D[nt], a0h, a1h, a2h, a3h, B.x, B.y);
                mma_f16(D[nt], a0l, a1l, a2l, a3l, B.x, B.y);
                mma_f16(D[nt], a0h, a1h, a2h, a3h, B.z, B.w);
            }
        }

        // layer 3: A = relu(D) hi/lo, B = W3 frags 8..15, init b3
        float Dn[4][4];
#pragma unroll
        for (int nt = 0; nt < 4; nt++) {
            const float2 b3v = *(const float2*)&sb[64 + 8 * nt + 2 * t];
            Dn[nt][0] = b3v.x; Dn[nt][1] = b3v.y;
            Dn[nt][2] = b3v.x; Dn[nt][3] = b3v.y;
        }
#pragma unroll
        for (int ks = 0; ks < 2; ks++) {
            uint32_t a0h, a1h, a2h, a3h, a0l, a1l, a2l, a3l;
            prelu_hilo2(D[2 * ks][0],     D[2 * ks][1],     a0h, a0l);
            prelu_hilo2(D[2 * ks][2],     D[2 * ks][3],     a1h, a1l);
            prelu_hilo2(D[2 * ks + 1][0], D[2 * ks + 1][1], a2h, a2l);
            prelu_hilo2(D[2 * ks + 1][2], D[2 * ks + 1][3], a3h, a3l);
#pragma unroll
            for (int nt = 0; nt < 4; nt++) {
                const uint4 B = swh[(8 + ks * 4 + nt) * 32 + lane];
                mma_f16(Dn[nt], a0h, a1h, a2h, a3h, B.x, B.y);
                mma_f16(Dn[nt], a0l, a1l, a2l, a3l, B.x, B.y);
                mma_f16(Dn[nt], a0h, a1h, a2h, a3h, B.z, B.w);
            }
        }

        // layer 4: A = relu(Dn) hi/lo, B = W4 frags 16..17, init b4, no relu
        float O[4];
        {
            const float2 b4v = *(const float2*)&sb[96 + 2 * t];
            O[0] = b4v.x; O[1] = b4v.y;
            O[2] = b4v.x; O[3] = b4v.y;
        }
#pragma unroll
        for (int ks = 0; ks < 2; ks++) {
            uint32_t a0h, a1h, a2h, a3h, a0l, a1l, a2l, a3l;
            prelu_hilo2(Dn[2 * ks][0],     Dn[2 * ks][1],     a0h, a0l);
            prelu_hilo2(Dn[2 * ks][2],     Dn[2 * ks][3],     a1h, a1l);
            prelu_hilo2(Dn[2 * ks + 1][0], Dn[2 * ks + 1][1], a2h, a2l);
            prelu_hilo2(Dn[2 * ks + 1][2], Dn[2 * ks + 1][3], a3h, a3l);
            const uint4 B = swh[(16 + ks) * 32 + lane];
            mma_f16(O, a0h, a1h, a2h, a3h, B.x, B.y);
            mma_f16(O, a0l, a1l, a2l, a3l, B.x, B.y);
            mma_f16(O, a0h, a1h, a2h, a3h, B.z, B.w);
        }

        // store: rows gq, gq+8 of this m-tile, cols 2t,2t+1 (valid cols < 4)
        if (t < 2) {
            const int p0 = blockIdx.x * 256 + warp * 32 + 16 * mt + gq;
            *(float2*)&out[p0 * 4 + 2 * t]       = make_float2(O[0], O[1]);
            *(float2*)&out[(p0 + 8) * 4 + 2 * t] = make_float2(O[2], O[3]);
        }
    }
}

// ---------------------------------------------------------------------------
extern "C" void kernel_launch(void* const* d_in, const int* in_sizes, int n_in,
                              void* d_out, int out_size)
{
    const float* coord = (const float*)d_in[0];
    const float* grid  = (const float*)d_in[1];
    const float* w1 = (const float*)d_in[2];
    const float* b1 = (const float*)d_in[3];
    const float* w2 = (const float*)d_in[4];
    const float* b2 = (const float*)d_in[5];
    const float* w3 = (const float*)d_in[6];
    const float* b3 = (const float*)d_in[7];
    const float* w4 = (const float*)d_in[8];
    const float* b4 = (const float*)d_in[9];
    float* out = (float*)d_out;

    prep_wfrag_kernel<<<16, 32>>>(w1);
    prep_whalf_kernel<<<18, 32>>>(w2, w3, w4);
    voxel_w1_kernel<<<NVOX / 256, 256>>>(grid);
    fused_field_kernel<<<NPTS / 256, 256>>>(coord, b1, b2, b3, b4, out);
}

// round 10
// speedup vs baseline: 1.8344x; 1.0155x over previous
#include <cuda_runtime.h>
#include <cuda_fp16.h>
#include <cstdint>

#define RES   128
#define FEAT  32
#define NVOX  (RES * RES * RES)           // 2,097,152 voxels
#define NPTS  (2048 * 1024)               // 2,097,152 points

// fp16 voxel tensor holding layer-1 pre-activations: vox[v*32+j] = (W1 @ g[:,v])[j]
__device__ __half g_vox16[(size_t)NVOX * FEAT];
// Split-fp16 B-fragments: W1 (0..7), W2 (8..15), W3 (16..23), W4 (24..25).
// Per lane: {hi_b0, hi_b1, lo_b0, lo_b1}.
__device__ uint4 g_whalf[26 * 32];

// ---------------------------------------------------------------------------
__device__ __forceinline__ void mma_f16(float d[4],
                                        uint32_t a0, uint32_t a1, uint32_t a2, uint32_t a3,
                                        uint32_t b0, uint32_t b1) {
    asm volatile("mma.sync.aligned.m16n8k16.row.col.f32.f16.f16.f32 "
                 "{%0,%1,%2,%3}, {%4,%5,%6,%7}, {%8,%9}, {%0,%1,%2,%3};"
                 : "+f"(d[0]), "+f"(d[1]), "+f"(d[2]), "+f"(d[3])
                 : "r"(a0), "r"(a1), "r"(a2), "r"(a3), "r"(b0), "r"(b1));
}

// hi/lo fp16 split of a float pair (packed f16x2 each)
__device__ __forceinline__ void hilo2(float x, float y, uint32_t& hi, uint32_t& lo) {
    const __half2 h = __floats2half2_rn(x, y);
    hi = *(const uint32_t*)&h;
    const float2 hf = __half22float2(h);
    const __half2 l = __floats2half2_rn(x - hf.x, y - hf.y);
    lo = *(const uint32_t*)&l;
}

// relu, then hi/lo split
__device__ __forceinline__ void prelu_hilo2(float x, float y, uint32_t& hi, uint32_t& lo) {
    hilo2(fmaxf(x, 0.0f), fmaxf(y, 0.0f), hi, lo);
}

// ---------------------------------------------------------------------------
// Prep (single kernel): split-fp16 B-fragments for all layers, m16n8k16 order.
// ---------------------------------------------------------------------------
__global__ void prep_whalf_kernel(const float* __restrict__ w1, const float* __restrict__ w2,
                                  const float* __restrict__ w3, const float* __restrict__ w4) {
    const int f = blockIdx.x;        // 0..25
    const int lane = threadIdx.x;
    const int g = lane >> 2, t = lane & 3;
    float v0 = 0.f, v1 = 0.f, v2 = 0.f, v3 = 0.f;
    if (f < 24) {
        const float* W = (f < 8) ? w1 : (f < 16) ? w2 : w3;
        const int r = f & 7, ks = r >> 2, nt = r & 3;
        const int row = 8 * nt + g, k = 16 * ks;
        v0 = W[row * 32 + k + 2 * t];
        v1 = W[row * 32 + k + 2 * t + 1];
        v2 = W[row * 32 + k + 2 * t + 8];
        v3 = W[row * 32 + k + 2 * t + 9];
    } else {
        const int ks = f - 24;
        if (g < 4) {
            v0 = w4[g * 32 + 16 * ks + 2 * t];
            v1 = w4[g * 32 + 16 * ks + 2 * t + 1];
            v2 = w4[g * 32 + 16 * ks + 2 * t + 8];
            v3 = w4[g * 32 + 16 * ks + 2 * t + 9];
        }
    }
    uint4 u;
    hilo2(v0, v1, u.x, u.z);
    hilo2(v2, v3, u.y, u.w);
    g_whalf[f * 32 + lane] = u;
}

// ---------------------------------------------------------------------------
// Voxel transform: grid (C,D,H,W) -> fp16 (D*H*W, 32) of W1 @ v.
// fp16 hi/lo split mma (error << fp16 output rounding). m-tile sequential,
// 4 blocks/SM. TC_STRIDE=260: fp16 A-frag LDS pattern (8t+gq) is a perfect
// bank permutation for all four k/row offsets.
// ---------------------------------------------------------------------------
#define TC_STRIDE 260
__global__ void __launch_bounds__(256, 4) voxel_w1_kernel(const float* __restrict__ g) {
    __shared__ float tile[32 * TC_STRIDE];     // 33,280 B  (c-major)
    __shared__ uint4 swh1[8 * 32];             //  4,096 B  (W1 frags)
    const int tid = threadIdx.x;
    const int v0 = blockIdx.x * 256;

    for (int i = tid; i < 8 * 32; i += 256) swh1[i] = g_whalf[i];

    // vectorized staging: 32 channels x 256 voxels = 2048 float4
#pragma unroll
    for (int i = 0; i < 8; i++) {
        const int idx = tid + i * 256;
        const int c = idx >> 6, v4 = idx & 63;
        const float4 val = *(const float4*)&g[(size_t)c * NVOX + v0 + v4 * 4];
        *(float4*)&tile[c * TC_STRIDE + v4 * 4] = val;
    }
    __syncthreads();

    const int warp = tid >> 5, lane = tid & 31;
    const int gq = lane >> 2, t = lane & 3;
    const int vb = warp * 32;

#pragma unroll
    for (int mt = 0; mt < 2; mt++) {
        const int r = vb + 16 * mt + gq;
        float D[4][4];
#pragma unroll
        for (int nt = 0; nt < 4; nt++)
#pragma unroll
            for (int i = 0; i < 4; i++) D[nt][i] = 0.0f;

#pragma unroll
        for (int ks = 0; ks < 2; ks++) {
            const int k = 16 * ks + 2 * t;
            uint32_t a0h, a0l, a1h, a1l, a2h, a2l, a3h, a3l;
            hilo2(tile[k * TC_STRIDE + r],           tile[(k + 1) * TC_STRIDE + r],     a0h, a0l);
            hilo2(tile[k * TC_STRIDE + r + 8],       tile[(k + 1) * TC_STRIDE + r + 8], a1h, a1l);
            hilo2(tile[(k + 8) * TC_STRIDE + r],     tile[(k + 9) * TC_STRIDE + r],     a2h, a2l);
            hilo2(tile[(k + 8) * TC_STRIDE + r + 8], tile[(k + 9) * TC_STRIDE + r + 8], a3h, a3l);
#pragma unroll
            for (int nt = 0; nt < 4; nt++) {
                const uint4 B = swh1[(ks * 4 + nt) * 32 + lane];
                mma_f16(D[nt], a0h, a1h, a2h, a3h, B.x, B.y);
                mma_f16(D[nt], a0l, a1l, a2l, a3l, B.x, B.y);
                mma_f16(D[nt], a0h, a1h, a2h, a3h, B.z, B.w);
            }
        }
#pragma unroll
        for (int nt = 0; nt < 4; nt++) {
            const int v = v0 + vb + 16 * mt + gq;
            const __half2 p0 = __floats2half2_rn(D[nt][0], D[nt][1]);
            const __half2 p1 = __floats2half2_rn(D[nt][2], D[nt][3]);
            *(__half2*)&g_vox16[(size_t)v * 32 + 8 * nt + 2 * t]       = p0;
            *(__half2*)&g_vox16[(size_t)(v + 8) * 32 + 8 * nt + 2 * t] = p1;
        }
    }
}

// ---------------------------------------------------------------------------
// Fused gather + 3 MLP layers (fp16 mma, hi/lo split operands),
// m-tile-sequential phase 2, 3 blocks/SM.
// ---------------------------------------------------------------------------
#define SV_STRIDE 36   // uints per point: 16 hi + 16 lo + 4 pad

__global__ void __launch_bounds__(256, 3) fused_field_kernel(
    const float* __restrict__ coord,
    const float* __restrict__ b1g, const float* __restrict__ b2g,
    const float* __restrict__ b3g, const float* __restrict__ b4g,
    float* __restrict__ out)
{
    __shared__ uint4 swh[26 * 32];             // 13,312 B
    __shared__ float sb[128];                  //    512 B
    __shared__ uint32_t svu[256 * SV_STRIDE];  // 36,864 B

    const int tid = threadIdx.x;
    {
        for (int i = tid; i < 26 * 32; i += 256) swh[i] = g_whalf[i];
        if (tid < 32) {
            sb[tid]      = b1g[tid];
            sb[32 + tid] = b2g[tid];
            sb[64 + tid] = b3g[tid];
            sb[96 + tid] = (tid < 4) ? b4g[tid] : 0.0f;
        }
    }
    __syncthreads();

    const int warp  = tid >> 5;
    const int lane  = tid & 31;
    const int chunk = lane & 3;        // 16B slice (8 channels) of 32 fp16 channels
    const int psub  = lane >> 2;       // point-of-8 in round

    // --- Phase 1: pipelined warp-cooperative gather -> split fp16 in svu ---
    float cr[4][3];
#pragma unroll
    for (int s = 0; s < 4; s++) {
        const int q   = (warp << 5) + (s << 3) + psub;
        const int pid = blockIdx.x * 256 + q;
        cr[s][0] = __ldg(&coord[pid * 3 + 0]);
        cr[s][1] = __ldg(&coord[pid * 3 + 1]);
        cr[s][2] = __ldg(&coord[pid * 3 + 2]);
    }

    float bb[8];
#pragma unroll
    for (int i = 0; i < 8; i++) bb[i] = sb[8 * chunk + i];   // b1 slice

#pragma unroll
    for (int s = 0; s < 4; s++) {
        const int q = (warp << 5) + (s << 3) + psub;

        const float fx = (cr[s][0] + 1.0f) * 64.0f - 0.5f;
        const float fy = (cr[s][1] + 1.0f) * 64.0f - 0.5f;
        const float fz = (cr[s][2] + 1.0f) * 64.0f - 0.5f;

        const float x0f = floorf(fx), y0f = floorf(fy), z0f = floorf(fz);
        const float tx = fx - x0f, ty = fy - y0f, tz = fz - z0f;
        const int x0 = (int)x0f, y0 = (int)y0f, z0 = (int)z0f;

        int   xs[2], ys[2], zs[2];
        float wx[2], wy[2], wz[2];
        xs[0] = max(x0, 0);        xs[1] = min(x0 + 1, RES - 1);
        ys[0] = max(y0, 0);        ys[1] = min(y0 + 1, RES - 1);
        zs[0] = max(z0, 0);        zs[1] = min(z0 + 1, RES - 1);
        wx[0] = (x0 >= 0)          ? (1.0f - tx) : 0.0f;
        wx[1] = (x0 + 1 <= RES - 1)? tx          : 0.0f;
        wy[0] = (y0 >= 0)          ? (1.0f - ty) : 0.0f;
        wy[1] = (y0 + 1 <= RES - 1)? ty          : 0.0f;
        wz[0] = (z0 >= 0)          ? (1.0f - tz) : 0.0f;
        wz[1] = (z0 + 1 <= RES - 1)? tz          : 0.0f;

        uint4 raw[8];
        float w8[8];
#pragma unroll
        for (int c = 0; c < 8; c++) {
            const int kx = c & 1, ky = (c >> 1) & 1, kz = c >> 2;
            const int vox = ((zs[kz] * RES + ys[ky]) * RES + xs[kx]);
            raw[c] = __ldg(((const uint4*)(g_vox16 + ((size_t)vox << 5))) + chunk);
            w8[c]  = wz[kz] * wy[ky] * wx[kx];
        }

        float acc[8];
#pragma unroll
        for (int i = 0; i < 8; i++) acc[i] = bb[i];          // bias folded in
#pragma unroll
        for (int c = 0; c < 8; c++) {
            const __half2* h2 = (const __half2*)&raw[c];
            const float2 f0 = __half22float2(h2[0]);
            const float2 f1 = __half22float2(h2[1]);
            const float2 f2 = __half22float2(h2[2]);
            const float2 f3 = __half22float2(h2[3]);
            const float w = w8[c];
            acc[0] = fmaf(w, f0.x, acc[0]);  acc[1] = fmaf(w, f0.y, acc[1]);
            acc[2] = fmaf(w, f1.x, acc[2]);  acc[3] = fmaf(w, f1.y, acc[3]);
            acc[4] = fmaf(w, f2.x, acc[4]);  acc[5] = fmaf(w, f2.y, acc[5]);
            acc[6] = fmaf(w, f3.x, acc[6]);  acc[7] = fmaf(w, f3.y, acc[7]);
        }
        uint4 hi, lo;
        prelu_hilo2(acc[0], acc[1], hi.x, lo.x);
        prelu_hilo2(acc[2], acc[3], hi.y, lo.y);
        prelu_hilo2(acc[4], acc[5], hi.z, lo.z);
        prelu_hilo2(acc[6], acc[7], hi.w, lo.w);
        *(uint4*)&svu[q * SV_STRIDE + 4 * chunk]      = hi;  // relu(h1) hi
        *(uint4*)&svu[q * SV_STRIDE + 16 + 4 * chunk] = lo;  // relu(h1) lo
    }
    __syncwarp();

    // --- Phase 2: layers 2..4, one m-tile at a time ---
    const int gq = lane >> 2, t = lane & 3;

#pragma unroll
    for (int mt = 0; mt < 2; mt++) {
        const int q0 = warp * 32 + 16 * mt + gq;

        // layer 2: A = svu hi/lo, B = W2 frags 8..15, init b2
        float D[4][4];
#pragma unroll
        for (int nt = 0; nt < 4; nt++) {
            const float2 b2v = *(const float2*)&sb[32 + 8 * nt + 2 * t];
            D[nt][0] = b2v.x; D[nt][1] = b2v.y;
            D[nt][2] = b2v.x; D[nt][3] = b2v.y;
        }
#pragma unroll
        for (int ks = 0; ks < 2; ks++) {
            const uint32_t a0h = svu[q0 * SV_STRIDE + 8 * ks + t];
            const uint32_t a1h = svu[(q0 + 8) * SV_STRIDE + 8 * ks + t];
            const uint32_t a2h = svu[q0 * SV_STRIDE + 8 * ks + t + 4];
            const uint32_t a3h = svu[(q0 + 8) * SV_STRIDE + 8 * ks + t + 4];
            const uint32_t a0l = svu[q0 * SV_STRIDE + 16 + 8 * ks + t];
            const uint32_t a1l = svu[(q0 + 8) * SV_STRIDE + 16 + 8 * ks + t];
            const uint32_t a2l = svu[q0 * SV_STRIDE + 16 + 8 * ks + t + 4];
            const uint32_t a3l = svu[(q0 + 8) * SV_STRIDE + 16 + 8 * ks + t + 4];
#pragma unroll
            for (int nt = 0; nt < 4; nt++) {
                const uint4 B = swh[(8 + ks * 4 + nt) * 32 + lane];
                mma_f16(D[nt], a0h, a1h, a2h, a3h, B.x, B.y);
                mma_f16(D[nt], a0l, a1l, a2l, a3l, B.x, B.y);
                mma_f16(D[nt], a0h, a1h, a2h, a3h, B.z, B.w);
            }
        }

        // layer 3: A = relu(D) hi/lo, B = W3 frags 16..23, init b3
        float Dn[4][4];
#pragma unroll
        for (int nt = 0; nt < 4; nt++) {
            const float2 b3v = *(const float2*)&sb[64 + 8 * nt + 2 * t];
            Dn[nt][0] = b3v.x; Dn[nt][1] = b3v.y;
            Dn[nt][2] = b3v.x; Dn[nt][3] = b3v.y;
        }
#pragma unroll
        for (int ks = 0; ks < 2; ks++) {
            uint32_t a0h, a1h, a2h, a3h, a0l, a1l, a2l, a3l;
            prelu_hilo2(D[2 * ks][0],     D[2 * ks][1],     a0h, a0l);
            prelu_hilo2(D[2 * ks][2],     D[2 * ks][3],     a1h, a1l);
            prelu_hilo2(D[2 * ks + 1][0], D[2 * ks + 1][1], a2h, a2l);
            prelu_hilo2(D[2 * ks + 1][2], D[2 * ks + 1][3], a3h, a3l);
#pragma unroll
            for (int nt = 0; nt < 4; nt++) {
                const uint4 B = swh[(16 + ks * 4 + nt) * 32 + lane];
                mma_f16(Dn[nt], a0h, a1h, a2h, a3h, B.x, B.y);
                mma_f16(Dn[nt], a0l, a1l, a2l, a3l, B.x, B.y);
                mma_f16(Dn[nt], a0h, a1h, a2h, a3h, B.z, B.w);
            }
        }

        // layer 4: A = relu(Dn) hi/lo, B = W4 frags 24..25, init b4, no relu
        float O[4];
        {
            const float2 b4v = *(const float2*)&sb[96 + 2 * t];
            O[0] = b4v.x; O[1] = b4v.y;
            O[2] = b4v.x; O[3] = b4v.y;
        }
#pragma unroll
        for (int ks = 0; ks < 2; ks++) {
            uint32_t a0h, a1h, a2h, a3h, a0l, a1l, a2l, a3l;
            prelu_hilo2(Dn[2 * ks][0],     Dn[2 * ks][1],     a0h, a0l);
            prelu_hilo2(Dn[2 * ks][2],     Dn[2 * ks][3],     a1h, a1l);
            prelu_hilo2(Dn[2 * ks + 1][0], Dn[2 * ks + 1][1], a2h, a2l);
            prelu_hilo2(Dn[2 * ks + 1][2], Dn[2 * ks + 1][3], a3h, a3l);
            const uint4 B = swh[(24 + ks) * 32 + lane];
            mma_f16(O, a0h, a1h, a2h, a3h, B.x, B.y);
            mma_f16(O, a0l, a1l, a2l, a3l, B.x, B.y);
            mma_f16(O, a0h, a1h, a2h, a3h, B.z, B.w);
        }

        // store: rows gq, gq+8 of this m-tile, cols 2t,2t+1 (valid cols < 4)
        if (t < 2) {
            const int p0 = blockIdx.x * 256 + warp * 32 + 16 * mt + gq;
            *(float2*)&out[p0 * 4 + 2 * t]       = make_float2(O[0], O[1]);
            *(float2*)&out[(p0 + 8) * 4 + 2 * t] = make_float2(O[2], O[3]);
        }
    }
}

// ---------------------------------------------------------------------------
extern "C" void kernel_launch(void* const* d_in, const int* in_sizes, int n_in,
                              void* d_out, int out_size)
{
    const float* coord = (const float*)d_in[0];
    const float* grid  = (const float*)d_in[1];
    const float* w1 = (const float*)d_in[2];
    const float* b1 = (const float*)d_in[3];
    const float* w2 = (const float*)d_in[4];
    const float* b2 = (const float*)d_in[5];
    const float* w3 = (const float*)d_in[6];
    const float* b3 = (const float*)d_in[7];
    const float* w4 = (const float*)d_in[8];
    const float* b4 = (const float*)d_in[9];
    float* out = (float*)d_out;

    prep_whalf_kernel<<<26, 32>>>(w1, w2, w3, w4);
    voxel_w1_kernel<<<NVOX / 256, 256>>>(grid);
    fused_field_kernel<<<NPTS / 256, 256>>>(coord, b1, b2, b3, b4, out);
}